// round 4
// baseline (speedup 1.0000x reference)
#include <cuda_runtime.h>
#include <cuda_bf16.h>

#define DIMC 768
#define SEQ  2048
#define BB   2
#define NH   12
#define HDD  64
#define MTOT (BB*SEQ)
#define UNITS (2*BB*NH)
#define C_EXP (0.125f * 1.4426950408889634f)
#define MD ((size_t)MTOT*DIMC)
#define WD ((size_t)DIMC*DIMC)

// ---------------- scratch ----------------------------------------------------
__device__ __nv_bfloat16 g_xhi[4*MTOT*DIMC];
__device__ __nv_bfloat16 g_xlo[4*MTOT*DIMC];
__device__ __nv_bfloat16 g_whi[4*DIMC*DIMC];
__device__ __nv_bfloat16 g_wlo[4*DIMC*DIMC];
__device__ __nv_bfloat16 g_qh[UNITS*SEQ*HDD], g_ql[UNITS*SEQ*HDD];
__device__ __nv_bfloat16 g_kh[UNITS*SEQ*HDD], g_kl[UNITS*SEQ*HDD];
__device__ __nv_bfloat16 g_vh[UNITS*SEQ*HDD], g_vl[UNITS*SEQ*HDD];
__device__ __nv_bfloat16 g_ohi[2*MTOT*DIMC];
__device__ __nv_bfloat16 g_olo[2*MTOT*DIMC];

__device__ __forceinline__ float fexp2(float x) {
    float y; asm("ex2.approx.ftz.f32 %0, %1;" : "=f"(y) : "f"(x)); return y;
}
__device__ __forceinline__ void split2(float v, __nv_bfloat16& h, __nv_bfloat16& l) {
    h = __float2bfloat16(v);
    l = __float2bfloat16(v - __bfloat162float(h));
}
__device__ __forceinline__ void packsplit(float a, float b, unsigned& hi, unsigned& lo) {
    union { __nv_bfloat162 v; unsigned u; } h, l;
    h.v = __floats2bfloat162_rn(a, b);
    float2 f = __bfloat1622float2(h.v);
    l.v = __floats2bfloat162_rn(a - f.x, b - f.y);
    hi = h.u; lo = l.u;
}
__device__ __forceinline__ void cp16(void* s, const void* g) {
    unsigned a = (unsigned)__cvta_generic_to_shared(s);
    asm volatile("cp.async.cg.shared.global [%0], [%1], 16;\n" :: "r"(a), "l"(g));
}
__device__ __forceinline__ void cp16u(unsigned s, const void* g) {
    asm volatile("cp.async.cg.shared.global [%0], [%1], 16;\n" :: "r"(s), "l"(g));
}
__device__ __forceinline__ void commitg() { asm volatile("cp.async.commit_group;\n"); }
__device__ __forceinline__ void waitg1()  { asm volatile("cp.async.wait_group 1;\n"); }
__device__ __forceinline__ void waitg2()  { asm volatile("cp.async.wait_group 2;\n"); }

__device__ __forceinline__ void mma16816(float* d, const unsigned* a, unsigned b0, unsigned b1) {
    asm volatile("mma.sync.aligned.m16n8k16.row.col.f32.bf16.bf16.f32 "
                 "{%0,%1,%2,%3}, {%4,%5,%6,%7}, {%8,%9}, {%0,%1,%2,%3};"
                 : "+f"(d[0]), "+f"(d[1]), "+f"(d[2]), "+f"(d[3])
                 : "r"(a[0]), "r"(a[1]), "r"(a[2]), "r"(a[3]), "r"(b0), "r"(b1));
}
__device__ __forceinline__ void ldsm4(unsigned* r, unsigned a) {
    asm volatile("ldmatrix.sync.aligned.m8n8.x4.shared.b16 {%0,%1,%2,%3}, [%4];"
                 : "=r"(r[0]), "=r"(r[1]), "=r"(r[2]), "=r"(r[3]) : "r"(a));
}
__device__ __forceinline__ void ldsm2(unsigned& r0, unsigned& r1, unsigned a) {
    asm volatile("ldmatrix.sync.aligned.m8n8.x2.shared.b16 {%0,%1}, [%2];"
                 : "=r"(r0), "=r"(r1) : "r"(a));
}
__device__ __forceinline__ void ldsm2t(unsigned& r0, unsigned& r1, unsigned a) {
    asm volatile("ldmatrix.sync.aligned.m8n8.x2.trans.shared.b16 {%0,%1}, [%2];"
                 : "=r"(r0), "=r"(r1) : "r"(a));
}
__device__ __forceinline__ unsigned swz(int row, int j) {
    return (unsigned)((row * 8 + (j ^ (row & 7))) << 4);
}

// ---------------- 1) mix + convert activations ------------------------------
__global__ void mixcvt_kernel(const float* __restrict__ x1,
                              const float* __restrict__ x2,
                              const float* __restrict__ sp) {
    int i = blockIdx.x * 256 + threadIdx.x;
    float s = sp[0];
    float a = x1[i], b = x2[i];
    float m0 = (1.0f - s) * a + s * b;
    float m1 = (1.0f - s) * b + s * a;
    split2(a,  g_xhi[i],          g_xlo[i]);
    split2(b,  g_xhi[MD   + i],   g_xlo[MD   + i]);
    split2(m0, g_xhi[2*MD + i],   g_xlo[2*MD + i]);
    split2(m1, g_xhi[3*MD + i],   g_xlo[3*MD + i]);
}

// ---------------- 2) convert weights ----------------------------------------
__global__ void wcvt_kernel(const float* __restrict__ Wq, const float* __restrict__ Wk,
                            const float* __restrict__ Wv, const float* __restrict__ Wo) {
    int i = blockIdx.x * 256 + threadIdx.x;
    int mat = blockIdx.y;
    const float* W = (mat == 0) ? Wq : (mat == 1) ? Wk : (mat == 2) ? Wv : Wo;
    split2(W[i], g_whi[mat*WD + i], g_wlo[mat*WD + i]);
}

// ---------------- shared GEMM body ------------------------------------------
template<bool HEAD_SCATTER>
__device__ __forceinline__ void gemm_body(
    __nv_bfloat16* sm,
    const __nv_bfloat16* __restrict__ Ahi, const __nv_bfloat16* __restrict__ Alo,
    const __nv_bfloat16* __restrict__ Bhi, const __nv_bfloat16* __restrict__ Blo,
    const float* __restrict__ bias,
    float* __restrict__ outf,
    __nv_bfloat16* __restrict__ oh, __nv_bfloat16* __restrict__ ol,
    int m0, int c0, int ubase)
{
    int t = threadIdx.x, lane = t & 31, w = t >> 5;
    int wm = w & 3, wn = w >> 2;
    int g = lane >> 2, c = lane & 3;

    const __nv_bfloat16* Ah_g = Ahi + (size_t)m0 * DIMC;
    const __nv_bfloat16* Al_g = Alo + (size_t)m0 * DIMC;
    const __nv_bfloat16* Bh_g = Bhi + (size_t)c0 * DIMC;
    const __nv_bfloat16* Bl_g = Blo + (size_t)c0 * DIMC;

    float acc[2][8][4];
#pragma unroll
    for (int mt = 0; mt < 2; mt++)
#pragma unroll
        for (int nt = 0; nt < 8; nt++)
#pragma unroll
            for (int j = 0; j < 4; j++) acc[mt][nt][j] = 0.0f;

    int row = t >> 1, half = t & 1;
    int so = row * 24 + half * 8;

    {
        size_t go = (size_t)row * DIMC + half * 8;
        __nv_bfloat16* b0 = sm;
        cp16(b0 + so,        Ah_g + go);
        cp16(b0 + 3072 + so, Al_g + go);
        cp16(b0 + 6144 + so, Bh_g + go);
        cp16(b0 + 9216 + so, Bl_g + go);
    }
    commitg();

    for (int ks = 0; ks < 48; ks++) {
        if (ks < 47) {
            size_t go = (size_t)row * DIMC + (ks + 1) * 16 + half * 8;
            __nv_bfloat16* bf = sm + ((ks + 1) & 1) * 12288;
            cp16(bf + so,        Ah_g + go);
            cp16(bf + 3072 + so, Al_g + go);
            cp16(bf + 6144 + so, Bh_g + go);
            cp16(bf + 9216 + so, Bl_g + go);
        }
        commitg();
        waitg1();
        __syncthreads();

        const unsigned* Aw  = (const unsigned*)(sm + (ks & 1) * 12288);
        const unsigned* Alw = Aw + 1536;
        const unsigned* Bw  = Aw + 3072;
        const unsigned* Blw = Aw + 4608;

        unsigned ah[2][4], al[2][4];
#pragma unroll
        for (int mt = 0; mt < 2; mt++) {
            int r = wm * 32 + mt * 16 + g;
            ah[mt][0] = Aw [r*12 + c];     ah[mt][1] = Aw [(r+8)*12 + c];
            ah[mt][2] = Aw [r*12 + c + 4]; ah[mt][3] = Aw [(r+8)*12 + c + 4];
            al[mt][0] = Alw[r*12 + c];     al[mt][1] = Alw[(r+8)*12 + c];
            al[mt][2] = Alw[r*12 + c + 4]; al[mt][3] = Alw[(r+8)*12 + c + 4];
        }
#pragma unroll
        for (int nt = 0; nt < 8; nt++) {
            int n = wn * 64 + nt * 8 + g;
            unsigned bh0 = Bw [n*12 + c], bh1 = Bw [n*12 + c + 4];
            unsigned bl0 = Blw[n*12 + c], bl1 = Blw[n*12 + c + 4];
            mma16816(acc[0][nt], ah[0], bh0, bh1);
            mma16816(acc[1][nt], ah[1], bh0, bh1);
            mma16816(acc[0][nt], ah[0], bl0, bl1);
            mma16816(acc[1][nt], ah[1], bl0, bl1);
            mma16816(acc[0][nt], al[0], bh0, bh1);
            mma16816(acc[1][nt], al[1], bh0, bh1);
        }
        __syncthreads();
    }

#pragma unroll
    for (int mt = 0; mt < 2; mt++) {
#pragma unroll
        for (int nt = 0; nt < 8; nt++) {
            int r0 = m0 + wm * 32 + mt * 16 + g;
            int col = c0 + wn * 64 + nt * 8 + 2 * c;
            float bb0 = bias[col], bb1 = bias[col + 1];
            float* A4 = acc[mt][nt];
            if (HEAD_SCATTER) {
                int h = col >> 6, d = col & 63;
                {
                    int bi = r0 >> 11, n = r0 & 2047;
                    size_t off = (((size_t)(ubase + bi*NH + h))*SEQ + n)*HDD + d;
                    unsigned hw, lw; packsplit(A4[0] + bb0, A4[1] + bb1, hw, lw);
                    *(unsigned*)(oh + off) = hw;
                    *(unsigned*)(ol + off) = lw;
                }
                {
                    int r1 = r0 + 8;
                    int bi = r1 >> 11, n = r1 & 2047;
                    size_t off = (((size_t)(ubase + bi*NH + h))*SEQ + n)*HDD + d;
                    unsigned hw, lw; packsplit(A4[2] + bb0, A4[3] + bb1, hw, lw);
                    *(unsigned*)(oh + off) = hw;
                    *(unsigned*)(ol + off) = lw;
                }
            } else {
                float2 v0 = make_float2(A4[0] + bb0, A4[1] + bb1);
                float2 v1 = make_float2(A4[2] + bb0, A4[3] + bb1);
                *(float2*)&outf[(size_t)r0 * DIMC + col]     = v0;
                *(float2*)&outf[(size_t)(r0+8) * DIMC + col] = v1;
            }
        }
    }
}

#define GEMM_SMEM (2 * 12288 * 2)

// ---------------- 3) fused QKV projection -----------------------------------
__global__ __launch_bounds__(256, 2)
void qkv_mma(const float* __restrict__ bq, const float* __restrict__ bk,
             const float* __restrict__ bv) {
    extern __shared__ __nv_bfloat16 smx[];
    int z = blockIdx.z, s = z / 3, which = z % 3;
    int amat = (which == 1) ? (2 + s) : s;
    const __nv_bfloat16* Ahi = g_xhi + (size_t)amat * MD;
    const __nv_bfloat16* Alo = g_xlo + (size_t)amat * MD;
    const __nv_bfloat16* Bhi = g_whi + (size_t)which * WD;
    const __nv_bfloat16* Blo = g_wlo + (size_t)which * WD;
    const float* bias = (which == 0) ? bq : (which == 1) ? bk : bv;
    __nv_bfloat16* oh = (which == 0) ? g_qh : (which == 1) ? g_kh : g_vh;
    __nv_bfloat16* ol = (which == 0) ? g_ql : (which == 1) ? g_kl : g_vl;
    gemm_body<true>(smx, Ahi, Alo, Bhi, Blo, bias, nullptr, oh, ol,
                    blockIdx.y * 128, blockIdx.x * 128, s * BB * NH);
}

// ---------------- 5) output projection --------------------------------------
__global__ __launch_bounds__(256, 2)
void oproj_mma(const float* __restrict__ bo, float* __restrict__ out) {
    extern __shared__ __nv_bfloat16 smx[];
    int s = blockIdx.z;
    gemm_body<false>(smx, g_ohi + (size_t)s * MD, g_olo + (size_t)s * MD,
                     g_whi + 3 * WD, g_wlo + 3 * WD, bo, out + (size_t)s * MD,
                     nullptr, nullptr, blockIdx.y * 128, blockIdx.x * 128, 0);
}

// ---------------- 4) flash attention (tensor cores) -------------------------
// 4 warps x 16 query rows = 64-query block; 64-key tiles, 3-stage cp.async.
// smem: stage s at s*32768: Kh(8K) Kl(8K) Vh(8K) Vl(8K).
// Q (hi @65536, lo @73728) staged into stage-2 region before the KV pipeline
// touches it (stage 2 first written at iteration 0, after Q-frag extraction).
#define AT_SMEM 98304

__global__ __launch_bounds__(128, 2)
void attn_mma() {
    extern __shared__ char smc[];
    unsigned sbase = (unsigned)__cvta_generic_to_shared(smc);
    int t = threadIdx.x, lane = t & 31, w = t >> 5;
    int g = lane >> 2, cc = lane & 3;
    int unit = blockIdx.y, qblk = blockIdx.x;

    const __nv_bfloat16* Qh_g = g_qh + (size_t)unit*SEQ*HDD + (size_t)qblk*64*HDD;
    const __nv_bfloat16* Ql_g = g_ql + (size_t)unit*SEQ*HDD + (size_t)qblk*64*HDD;
    const __nv_bfloat16* Kh_g = g_kh + (size_t)unit*SEQ*HDD;
    const __nv_bfloat16* Kl_g = g_kl + (size_t)unit*SEQ*HDD;
    const __nv_bfloat16* Vh_g = g_vh + (size_t)unit*SEQ*HDD;
    const __nv_bfloat16* Vl_g = g_vl + (size_t)unit*SEQ*HDD;

    int row = t >> 1, j0 = (t & 1) * 4;

    // ---- G0: Q (hi+lo) + KV tile 0 ----
#pragma unroll
    for (int jj = 0; jj < 4; jj++) {
        int j = j0 + jj;
        unsigned so = swz(row, j);
        size_t gq = (size_t)row * 64 + j * 8;
        cp16u(sbase + 65536 + so, Qh_g + gq);
        cp16u(sbase + 73728 + so, Ql_g + gq);
        cp16u(sbase + so,         Kh_g + gq);
        cp16u(sbase + 8192  + so, Kl_g + gq);
        cp16u(sbase + 16384 + so, Vh_g + gq);
        cp16u(sbase + 24576 + so, Vl_g + gq);
    }
    commitg();
    // ---- G1: KV tile 1 ----
#pragma unroll
    for (int jj = 0; jj < 4; jj++) {
        int j = j0 + jj;
        unsigned so = swz(row, j);
        size_t gk = (size_t)(64 + row) * 64 + j * 8;
        cp16u(sbase + 32768 + so, Kh_g + gk);
        cp16u(sbase + 40960 + so, Kl_g + gk);
        cp16u(sbase + 49152 + so, Vh_g + gk);
        cp16u(sbase + 57344 + so, Vl_g + gk);
    }
    commitg();
    waitg1();          // G0 (Q + tile0) complete
    __syncthreads();

    // ---- Q fragments to registers ----
    unsigned qh[4][4], ql[4][4];
    int R0 = w * 16;
    {
        int mi = lane >> 3, rr = lane & 7;
#pragma unroll
        for (int kk = 0; kk < 4; kk++) {
            int rowq = R0 + (mi & 1) * 8 + rr;
            int jc = kk * 2 + (mi >> 1);
            unsigned a = sbase + 65536 + swz(rowq, jc);
            ldsm4(qh[kk], a);
            ldsm4(ql[kk], a + 8192);
        }
    }
    __syncthreads();   // Q reads done before iter 0 writes stage 2

    float O[8][4];
#pragma unroll
    for (int nt = 0; nt < 8; nt++)
#pragma unroll
        for (int j = 0; j < 4; j++) O[nt][j] = 0.0f;
    float m0 = -1e30f, m1 = -1e30f, l0 = 0.0f, l1 = 0.0f;

    for (int kt = 0; kt < 32; kt++) {
        if (kt < 30) {
            int st = (kt + 2) % 3;
            unsigned sb2 = sbase + (unsigned)st * 32768;
#pragma unroll
            for (int jj = 0; jj < 4; jj++) {
                int j = j0 + jj;
                unsigned so = swz(row, j);
                size_t gk = (size_t)((kt + 2) * 64 + row) * 64 + j * 8;
                cp16u(sb2 + so,         Kh_g + gk);
                cp16u(sb2 + 8192  + so, Kl_g + gk);
                cp16u(sb2 + 16384 + so, Vh_g + gk);
                cp16u(sb2 + 24576 + so, Vl_g + gk);
            }
        }
        commitg();
        waitg2();      // stage kt's group complete
        __syncthreads();

        unsigned sb = sbase + (unsigned)(kt % 3) * 32768;

        // ---- S = Q K^T (3-mma hi/lo) ----
        float S[8][4];
#pragma unroll
        for (int nt = 0; nt < 8; nt++)
#pragma unroll
            for (int j = 0; j < 4; j++) S[nt][j] = 0.0f;

        {
            int rr = lane & 7, hf = (lane >> 3) & 1;
#pragma unroll
            for (int nt = 0; nt < 8; nt++) {
                int rowk = nt * 8 + rr;
#pragma unroll
                for (int kk = 0; kk < 4; kk++) {
                    unsigned ka = sb + swz(rowk, kk * 2 + hf);
                    unsigned bh0, bh1, bl0, bl1;
                    ldsm2(bh0, bh1, ka);
                    ldsm2(bl0, bl1, ka + 8192);
                    mma16816(S[nt], qh[kk], bh0, bh1);
                    mma16816(S[nt], qh[kk], bl0, bl1);
                    mma16816(S[nt], ql[kk], bh0, bh1);
                }
            }
        }

        // ---- online softmax ----
        float mx0 = -1e30f, mx1 = -1e30f;
#pragma unroll
        for (int nt = 0; nt < 8; nt++) {
            mx0 = fmaxf(mx0, fmaxf(S[nt][0], S[nt][1]));
            mx1 = fmaxf(mx1, fmaxf(S[nt][2], S[nt][3]));
        }
        mx0 = fmaxf(mx0, __shfl_xor_sync(0xffffffffu, mx0, 1));
        mx0 = fmaxf(mx0, __shfl_xor_sync(0xffffffffu, mx0, 2));
        mx1 = fmaxf(mx1, __shfl_xor_sync(0xffffffffu, mx1, 1));
        mx1 = fmaxf(mx1, __shfl_xor_sync(0xffffffffu, mx1, 2));
        float m0n = fmaxf(m0, mx0), m1n = fmaxf(m1, mx1);
        float al0 = fexp2((m0 - m0n) * C_EXP);
        float al1 = fexp2((m1 - m1n) * C_EXP);
        float mc0 = m0n * C_EXP, mc1 = m1n * C_EXP;
        l0 *= al0; l1 *= al1;
#pragma unroll
        for (int nt = 0; nt < 8; nt++) {
            float p0 = fexp2(fmaf(S[nt][0], C_EXP, -mc0));
            float p1 = fexp2(fmaf(S[nt][1], C_EXP, -mc0));
            float p2 = fexp2(fmaf(S[nt][2], C_EXP, -mc1));
            float p3 = fexp2(fmaf(S[nt][3], C_EXP, -mc1));
            l0 += p0 + p1; l1 += p2 + p3;
            S[nt][0] = p0; S[nt][1] = p1; S[nt][2] = p2; S[nt][3] = p3;
            O[nt][0] *= al0; O[nt][1] *= al0; O[nt][2] *= al1; O[nt][3] *= al1;
        }
        m0 = m0n; m1 = m1n;

        // ---- pack P into A-fragments (hi/lo) ----
        unsigned ph[4][4], pl[4][4];
#pragma unroll
        for (int tt = 0; tt < 4; tt++) {
            packsplit(S[2*tt][0],   S[2*tt][1],   ph[tt][0], pl[tt][0]);
            packsplit(S[2*tt][2],   S[2*tt][3],   ph[tt][1], pl[tt][1]);
            packsplit(S[2*tt+1][0], S[2*tt+1][1], ph[tt][2], pl[tt][2]);
            packsplit(S[2*tt+1][2], S[2*tt+1][3], ph[tt][3], pl[tt][3]);
        }

        // ---- O += P V  (V via ldmatrix.trans; 3-mma hi/lo) ----
        {
            int vlr = lane & 15;
#pragma unroll
            for (int tt = 0; tt < 4; tt++) {
                int rowv = tt * 16 + vlr;
#pragma unroll
                for (int nd = 0; nd < 8; nd++) {
                    unsigned va = sb + 16384 + swz(rowv, nd);
                    unsigned vh0, vh1, vl0, vl1;
                    ldsm2t(vh0, vh1, va);
                    ldsm2t(vl0, vl1, va + 8192);
                    mma16816(O[nd], ph[tt], vh0, vh1);
                    mma16816(O[nd], ph[tt], vl0, vl1);
                    mma16816(O[nd], pl[tt], vh0, vh1);
                }
            }
        }
        __syncthreads();   // readers done before this stage is refilled
    }

    // ---- epilogue ----
    l0 += __shfl_xor_sync(0xffffffffu, l0, 1);
    l0 += __shfl_xor_sync(0xffffffffu, l0, 2);
    l1 += __shfl_xor_sync(0xffffffffu, l1, 1);
    l1 += __shfl_xor_sync(0xffffffffu, l1, 2);
    float inv0 = 1.0f / l0, inv1 = 1.0f / l1;

    int s_ = unit / (BB*NH);
    int bh_ = unit % (BB*NH);
    int bi = bh_ / NH, h = bh_ % NH;
    int tok0 = qblk * 64 + R0 + g;
    int tok1 = tok0 + 8;

#pragma unroll
    for (int nd = 0; nd < 8; nd++) {
        int d = nd * 8 + 2 * cc;
        unsigned hw, lw;
        size_t off0 = (size_t)s_ * MD + (size_t)(bi*SEQ + tok0) * DIMC + h*64 + d;
        packsplit(O[nd][0] * inv0, O[nd][1] * inv0, hw, lw);
        *(unsigned*)(g_ohi + off0) = hw;
        *(unsigned*)(g_olo + off0) = lw;
        size_t off1 = (size_t)s_ * MD + (size_t)(bi*SEQ + tok1) * DIMC + h*64 + d;
        packsplit(O[nd][2] * inv1, O[nd][3] * inv1, hw, lw);
        *(unsigned*)(g_ohi + off1) = hw;
        *(unsigned*)(g_olo + off1) = lw;
    }
}

// ---------------- launch -----------------------------------------------------
extern "C" void kernel_launch(void* const* d_in, const int* in_sizes, int n_in,
                              void* d_out, int out_size) {
    const float* x1 = (const float*)d_in[0];
    const float* x2 = (const float*)d_in[1];
    const float* Wq = (const float*)d_in[2];
    const float* bq = (const float*)d_in[3];
    const float* Wk = (const float*)d_in[4];
    const float* bk = (const float*)d_in[5];
    const float* Wv = (const float*)d_in[6];
    const float* bv = (const float*)d_in[7];
    const float* Wo = (const float*)d_in[8];
    const float* bo = (const float*)d_in[9];
    const float* cs = (const float*)d_in[10];

    cudaFuncSetAttribute(qkv_mma,   cudaFuncAttributeMaxDynamicSharedMemorySize, GEMM_SMEM);
    cudaFuncSetAttribute(oproj_mma, cudaFuncAttributeMaxDynamicSharedMemorySize, GEMM_SMEM);
    cudaFuncSetAttribute(attn_mma,  cudaFuncAttributeMaxDynamicSharedMemorySize, AT_SMEM);

    mixcvt_kernel<<<(MTOT * DIMC) / 256, 256>>>(x1, x2, cs);
    wcvt_kernel<<<dim3((DIMC * DIMC) / 256, 4), 256>>>(Wq, Wk, Wv, Wo);

    qkv_mma<<<dim3(6, 32, 6), 256, GEMM_SMEM>>>(bq, bk, bv);

    attn_mma<<<dim3(32, 48), 128, AT_SMEM>>>();

    oproj_mma<<<dim3(6, 32, 2), 256, GEMM_SMEM>>>(bo, (float*)d_out);
}

// round 6
// speedup vs baseline: 1.1215x; 1.1215x over previous
#include <cuda_runtime.h>
#include <cuda_bf16.h>

#define DIMC 768
#define SEQ  2048
#define BB   2
#define NH   12
#define HDD  64
#define MTOT (BB*SEQ)
#define UNITS (2*BB*NH)
#define C_EXP (0.125f * 1.4426950408889634f)
#define MD ((size_t)MTOT*DIMC)
#define WD ((size_t)DIMC*DIMC)

// ---------------- scratch ----------------------------------------------------
__device__ __nv_bfloat16 g_xhi[4*MTOT*DIMC];
__device__ __nv_bfloat16 g_xlo[4*MTOT*DIMC];
__device__ __nv_bfloat16 g_whi[4*DIMC*DIMC];
__device__ __nv_bfloat16 g_wlo[4*DIMC*DIMC];
__device__ __nv_bfloat16 g_qh[UNITS*SEQ*HDD], g_ql[UNITS*SEQ*HDD];
__device__ __nv_bfloat16 g_kh[UNITS*SEQ*HDD], g_kl[UNITS*SEQ*HDD];
__device__ __nv_bfloat16 g_vh[UNITS*SEQ*HDD], g_vl[UNITS*SEQ*HDD];
__device__ __nv_bfloat16 g_ohi[2*MTOT*DIMC];
__device__ __nv_bfloat16 g_olo[2*MTOT*DIMC];

__device__ __forceinline__ float fexp2(float x) {
    float y; asm("ex2.approx.ftz.f32 %0, %1;" : "=f"(y) : "f"(x)); return y;
}
__device__ __forceinline__ void split2(float v, __nv_bfloat16& h, __nv_bfloat16& l) {
    h = __float2bfloat16(v);
    l = __float2bfloat16(v - __bfloat162float(h));
}
__device__ __forceinline__ void packsplit(float a, float b, unsigned& hi, unsigned& lo) {
    union { __nv_bfloat162 v; unsigned u; } h, l;
    h.v = __floats2bfloat162_rn(a, b);
    float2 f = __bfloat1622float2(h.v);
    l.v = __floats2bfloat162_rn(a - f.x, b - f.y);
    hi = h.u; lo = l.u;
}
__device__ __forceinline__ void cp16u(unsigned s, const void* g) {
    asm volatile("cp.async.cg.shared.global [%0], [%1], 16;\n" :: "r"(s), "l"(g));
}
__device__ __forceinline__ void commitg() { asm volatile("cp.async.commit_group;\n"); }
__device__ __forceinline__ void waitg1()  { asm volatile("cp.async.wait_group 1;\n"); }
__device__ __forceinline__ void waitg0()  { asm volatile("cp.async.wait_group 0;\n"); }

__device__ __forceinline__ void mma16816(float* d, const unsigned* a, unsigned b0, unsigned b1) {
    asm volatile("mma.sync.aligned.m16n8k16.row.col.f32.bf16.bf16.f32 "
                 "{%0,%1,%2,%3}, {%4,%5,%6,%7}, {%8,%9}, {%0,%1,%2,%3};"
                 : "+f"(d[0]), "+f"(d[1]), "+f"(d[2]), "+f"(d[3])
                 : "r"(a[0]), "r"(a[1]), "r"(a[2]), "r"(a[3]), "r"(b0), "r"(b1));
}
__device__ __forceinline__ void ldsm4(unsigned* r, unsigned a) {
    asm volatile("ldmatrix.sync.aligned.m8n8.x4.shared.b16 {%0,%1,%2,%3}, [%4];"
                 : "=r"(r[0]), "=r"(r[1]), "=r"(r[2]), "=r"(r[3]) : "r"(a));
}
__device__ __forceinline__ void ldsm2(unsigned& r0, unsigned& r1, unsigned a) {
    asm volatile("ldmatrix.sync.aligned.m8n8.x2.shared.b16 {%0,%1}, [%2];"
                 : "=r"(r0), "=r"(r1) : "r"(a));
}
__device__ __forceinline__ void ldsm2t(unsigned& r0, unsigned& r1, unsigned a) {
    asm volatile("ldmatrix.sync.aligned.m8n8.x2.trans.shared.b16 {%0,%1}, [%2];"
                 : "=r"(r0), "=r"(r1) : "r"(a));
}
// swizzled smem chunk offset (chunk = 16B; 8 chunks per 64-bf16 row)
__device__ __forceinline__ unsigned swz(int row, int j) {
    return (unsigned)((row * 8 + (j ^ (row & 7))) << 4);
}

// ---------------- 1) mix + convert activations ------------------------------
__global__ void mixcvt_kernel(const float* __restrict__ x1,
                              const float* __restrict__ x2,
                              const float* __restrict__ sp) {
    int i = blockIdx.x * 256 + threadIdx.x;
    float s = sp[0];
    float a = x1[i], b = x2[i];
    float m0 = (1.0f - s) * a + s * b;
    float m1 = (1.0f - s) * b + s * a;
    split2(a,  g_xhi[i],          g_xlo[i]);
    split2(b,  g_xhi[MD   + i],   g_xlo[MD   + i]);
    split2(m0, g_xhi[2*MD + i],   g_xlo[2*MD + i]);
    split2(m1, g_xhi[3*MD + i],   g_xlo[3*MD + i]);
}

// ---------------- 2) convert weights ----------------------------------------
__global__ void wcvt_kernel(const float* __restrict__ Wq, const float* __restrict__ Wk,
                            const float* __restrict__ Wv, const float* __restrict__ Wo) {
    int i = blockIdx.x * 256 + threadIdx.x;
    int mat = blockIdx.y;
    const float* W = (mat == 0) ? Wq : (mat == 1) ? Wk : (mat == 2) ? Wv : Wo;
    split2(W[i], g_whi[mat*WD + i], g_wlo[mat*WD + i]);
}

// ---------------- GEMM: 128x128 tile, ldmatrix-fed mma.sync ------------------
// K = 768 in 12 blocks of 64; cp.async double-buffered (2 x 64KB stages).
// Stage layout: Ah @0, Al @16384, Bh @32768, Bl @49152; each 128 rows x 64 bf16
// in the swz() XOR-swizzled layout (conflict-free for cp.async stores and
// ldmatrix reads). 8 warps: wm = w&3 (32-row group), wn = w>>2 (64-col group).
#define GEMM_SMEM (2 * 65536)

template<bool HEAD_SCATTER>
__device__ __forceinline__ void gemm_body(
    const __nv_bfloat16* __restrict__ Ahi, const __nv_bfloat16* __restrict__ Alo,
    const __nv_bfloat16* __restrict__ Bhi, const __nv_bfloat16* __restrict__ Blo,
    const float* __restrict__ bias,
    float* __restrict__ outf,
    __nv_bfloat16* __restrict__ oh, __nv_bfloat16* __restrict__ ol,
    int m0, int c0, int ubase)
{
    extern __shared__ char smg[];
    unsigned sbase = (unsigned)__cvta_generic_to_shared(smg);
    int t = threadIdx.x, lane = t & 31, w = t >> 5;
    int wm = w & 3, wn = w >> 2;
    int g = lane >> 2, c = lane & 3;
    int mi = lane >> 3, rr = lane & 7;

    const __nv_bfloat16* Ah_g = Ahi + (size_t)m0 * DIMC;
    const __nv_bfloat16* Al_g = Alo + (size_t)m0 * DIMC;
    const __nv_bfloat16* Bh_g = Bhi + (size_t)c0 * DIMC;
    const __nv_bfloat16* Bl_g = Blo + (size_t)c0 * DIMC;

    float acc[2][8][4];
#pragma unroll
    for (int mt = 0; mt < 2; mt++)
#pragma unroll
        for (int nt = 0; nt < 8; nt++)
#pragma unroll
            for (int j = 0; j < 4; j++) acc[mt][nt][j] = 0.0f;

    int lrow = t >> 1, lj0 = (t & 1) * 4;

    // prologue: k-block 0 -> stage 0
#pragma unroll
    for (int jj = 0; jj < 4; jj++) {
        int j = lj0 + jj;
        unsigned so = swz(lrow, j);
        size_t go = (size_t)lrow * DIMC + j * 8;
        cp16u(sbase + so,         Ah_g + go);
        cp16u(sbase + 16384 + so, Al_g + go);
        cp16u(sbase + 32768 + so, Bh_g + go);
        cp16u(sbase + 49152 + so, Bl_g + go);
    }
    commitg();

    for (int kb = 0; kb < 12; kb++) {
        if (kb < 11) {
            unsigned st = sbase + ((kb + 1) & 1) * 65536;
#pragma unroll
            for (int jj = 0; jj < 4; jj++) {
                int j = lj0 + jj;
                unsigned so = swz(lrow, j);
                size_t go = (size_t)lrow * DIMC + (kb + 1) * 64 + j * 8;
                cp16u(st + so,         Ah_g + go);
                cp16u(st + 16384 + so, Al_g + go);
                cp16u(st + 32768 + so, Bh_g + go);
                cp16u(st + 49152 + so, Bl_g + go);
            }
        }
        commitg();
        waitg1();
        __syncthreads();

        unsigned sb = sbase + (kb & 1) * 65536;

#pragma unroll
        for (int kk = 0; kk < 4; kk++) {
            // A fragments: m16k16 via ldsm4 (rows = m, chunk = k-half)
            int rowa = wm * 32 + (mi & 1) * 8 + rr;
            int jc = kk * 2 + (mi >> 1);
            unsigned ah0[4], ah1[4], al0[4], al1[4];
            ldsm4(ah0, sb + swz(rowa, jc));
            ldsm4(ah1, sb + swz(rowa + 16, jc));
            ldsm4(al0, sb + 16384 + swz(rowa, jc));
            ldsm4(al1, sb + 16384 + swz(rowa + 16, jc));
#pragma unroll
            for (int nt2 = 0; nt2 < 4; nt2++) {
                // B fragments: 2 n8-frags (n16 x k16) via ldsm4
                int rowb = wn * 64 + nt2 * 16 + (mi >> 1) * 8 + rr;
                int jb = kk * 2 + (mi & 1);
                unsigned bh[4], bl[4];
                ldsm4(bh, sb + 32768 + swz(rowb, jb));
                ldsm4(bl, sb + 49152 + swz(rowb, jb));
                int n0 = nt2 * 2, n1 = nt2 * 2 + 1;
                // hi*hi
                mma16816(acc[0][n0], ah0, bh[0], bh[1]);
                mma16816(acc[0][n1], ah0, bh[2], bh[3]);
                mma16816(acc[1][n0], ah1, bh[0], bh[1]);
                mma16816(acc[1][n1], ah1, bh[2], bh[3]);
                // hi*lo
                mma16816(acc[0][n0], ah0, bl[0], bl[1]);
                mma16816(acc[0][n1], ah0, bl[2], bl[3]);
                mma16816(acc[1][n0], ah1, bl[0], bl[1]);
                mma16816(acc[1][n1], ah1, bl[2], bl[3]);
                // lo*hi
                mma16816(acc[0][n0], al0, bh[0], bh[1]);
                mma16816(acc[0][n1], al0, bh[2], bh[3]);
                mma16816(acc[1][n0], al1, bh[0], bh[1]);
                mma16816(acc[1][n1], al1, bh[2], bh[3]);
            }
        }
        __syncthreads();
    }

    // ---- epilogue ----
#pragma unroll
    for (int mt = 0; mt < 2; mt++) {
#pragma unroll
        for (int nt = 0; nt < 8; nt++) {
            int r0 = m0 + wm * 32 + mt * 16 + g;
            int col = c0 + wn * 64 + nt * 8 + 2 * c;
            float bb0 = bias[col], bb1 = bias[col + 1];
            float* A4 = acc[mt][nt];
            if (HEAD_SCATTER) {
                int h = col >> 6, d = col & 63;
                {
                    int bi = r0 >> 11, n = r0 & 2047;
                    size_t off = (((size_t)(ubase + bi*NH + h))*SEQ + n)*HDD + d;
                    unsigned hw, lw; packsplit(A4[0] + bb0, A4[1] + bb1, hw, lw);
                    *(unsigned*)(oh + off) = hw;
                    *(unsigned*)(ol + off) = lw;
                }
                {
                    int r1 = r0 + 8;
                    int bi = r1 >> 11, n = r1 & 2047;
                    size_t off = (((size_t)(ubase + bi*NH + h))*SEQ + n)*HDD + d;
                    unsigned hw, lw; packsplit(A4[2] + bb0, A4[3] + bb1, hw, lw);
                    *(unsigned*)(oh + off) = hw;
                    *(unsigned*)(ol + off) = lw;
                }
            } else {
                float2 v0 = make_float2(A4[0] + bb0, A4[1] + bb1);
                float2 v1 = make_float2(A4[2] + bb0, A4[3] + bb1);
                *(float2*)&outf[(size_t)r0 * DIMC + col]     = v0;
                *(float2*)&outf[(size_t)(r0+8) * DIMC + col] = v1;
            }
        }
    }
}

// ---------------- 3) fused QKV projection -----------------------------------
__global__ __launch_bounds__(256, 1)
void qkv_mma(const float* __restrict__ bq, const float* __restrict__ bk,
             const float* __restrict__ bv) {
    int z = blockIdx.z, s = z / 3, which = z % 3;
    int amat = (which == 1) ? (2 + s) : s;
    const __nv_bfloat16* Ahi = g_xhi + (size_t)amat * MD;
    const __nv_bfloat16* Alo = g_xlo + (size_t)amat * MD;
    const __nv_bfloat16* Bhi = g_whi + (size_t)which * WD;
    const __nv_bfloat16* Blo = g_wlo + (size_t)which * WD;
    const float* bias = (which == 0) ? bq : (which == 1) ? bk : bv;
    __nv_bfloat16* oh = (which == 0) ? g_qh : (which == 1) ? g_kh : g_vh;
    __nv_bfloat16* ol = (which == 0) ? g_ql : (which == 1) ? g_kl : g_vl;
    gemm_body<true>(Ahi, Alo, Bhi, Blo, bias, nullptr, oh, ol,
                    blockIdx.y * 128, blockIdx.x * 128, s * BB * NH);
}

// ---------------- 5) output projection --------------------------------------
__global__ __launch_bounds__(256, 1)
void oproj_mma(const float* __restrict__ bo, float* __restrict__ out) {
    int s = blockIdx.z;
    gemm_body<false>(g_ohi + (size_t)s * MD, g_olo + (size_t)s * MD,
                     g_whi + 3 * WD, g_wlo + 3 * WD, bo, out + (size_t)s * MD,
                     nullptr, nullptr, blockIdx.y * 128, blockIdx.x * 128, 0);
}

// ---------------- 4) flash attention (R3 kernel: 8 warps/128q, 2-stage) -----
#define AT_SMEM 65536

__global__ __launch_bounds__(256, 1)
void attn_mma() {
    extern __shared__ char smca[];
    unsigned sbase = (unsigned)__cvta_generic_to_shared(smca);
    int t = threadIdx.x, lane = t & 31, w = t >> 5;
    int g = lane >> 2, cc = lane & 3;
    int unit = blockIdx.y, qblk = blockIdx.x;

    const __nv_bfloat16* Qh_g = g_qh + (size_t)unit*SEQ*HDD + (size_t)qblk*128*HDD;
    const __nv_bfloat16* Ql_g = g_ql + (size_t)unit*SEQ*HDD + (size_t)qblk*128*HDD;
    const __nv_bfloat16* Kh_g = g_kh + (size_t)unit*SEQ*HDD;
    const __nv_bfloat16* Kl_g = g_kl + (size_t)unit*SEQ*HDD;
    const __nv_bfloat16* Vh_g = g_vh + (size_t)unit*SEQ*HDD;
    const __nv_bfloat16* Vl_g = g_vl + (size_t)unit*SEQ*HDD;

    {
        int row = t >> 1, j0 = (t & 1) * 4;
#pragma unroll
        for (int jj = 0; jj < 4; jj++) {
            int j = j0 + jj;
            cp16u(sbase + 32768 + swz(row, j), Qh_g + row*64 + j*8);
            cp16u(sbase + 49152 + swz(row, j), Ql_g + row*64 + j*8);
        }
    }
    commitg(); waitg0();
    __syncthreads();

    unsigned qh[4][4], ql[4][4];
    int R0 = w * 16;
    {
        int mi = lane >> 3, rr = lane & 7;
#pragma unroll
        for (int kk = 0; kk < 4; kk++) {
            int rowq = R0 + (mi & 1) * 8 + rr;
            int jc = kk * 2 + (mi >> 1);
            unsigned a = sbase + 32768 + swz(rowq, jc);
            ldsm4(qh[kk], a);
            ldsm4(ql[kk], a + 16384);
        }
    }
    __syncthreads();

    float O[8][4];
#pragma unroll
    for (int nt = 0; nt < 8; nt++)
#pragma unroll
        for (int j = 0; j < 4; j++) O[nt][j] = 0.0f;
    float m0 = -1e30f, m1 = -1e30f, l0 = 0.0f, l1 = 0.0f;

    int krow = t >> 2, kj0 = (t & 3) * 2;

#pragma unroll
    for (int jj = 0; jj < 2; jj++) {
        int j = kj0 + jj;
        unsigned so = swz(krow, j);
        size_t go = (size_t)krow * 64 + j * 8;
        cp16u(sbase + so,         Kh_g + go);
        cp16u(sbase + 8192  + so, Kl_g + go);
        cp16u(sbase + 16384 + so, Vh_g + go);
        cp16u(sbase + 24576 + so, Vl_g + go);
    }
    commitg();

    for (int kt = 0; kt < 32; kt++) {
        if (kt < 31) {
            unsigned sb2 = sbase + ((kt + 1) & 1) * 32768;
#pragma unroll
            for (int jj = 0; jj < 2; jj++) {
                int j = kj0 + jj;
                unsigned so = swz(krow, j);
                size_t go = (size_t)((kt + 1) * 64 + krow) * 64 + j * 8;
                cp16u(sb2 + so,         Kh_g + go);
                cp16u(sb2 + 8192  + so, Kl_g + go);
                cp16u(sb2 + 16384 + so, Vh_g + go);
                cp16u(sb2 + 24576 + so, Vl_g + go);
            }
        }
        commitg();
        waitg1();
        __syncthreads();

        unsigned sb = sbase + (kt & 1) * 32768;

        float S[8][4];
#pragma unroll
        for (int nt = 0; nt < 8; nt++)
#pragma unroll
            for (int j = 0; j < 4; j++) S[nt][j] = 0.0f;

        {
            int rr = lane & 7, hf = (lane >> 3) & 1;
#pragma unroll
            for (int nt = 0; nt < 8; nt++) {
                int rowk = nt * 8 + rr;
#pragma unroll
                for (int kk = 0; kk < 4; kk++) {
                    unsigned ka = sb + swz(rowk, kk * 2 + hf);
                    unsigned bh0, bh1, bl0, bl1;
                    ldsm2(bh0, bh1, ka);
                    ldsm2(bl0, bl1, ka + 8192);
                    mma16816(S[nt], qh[kk], bh0, bh1);
                    mma16816(S[nt], qh[kk], bl0, bl1);
                    mma16816(S[nt], ql[kk], bh0, bh1);
                }
            }
        }

        float mx0 = -1e30f, mx1 = -1e30f;
#pragma unroll
        for (int nt = 0; nt < 8; nt++) {
            mx0 = fmaxf(mx0, fmaxf(S[nt][0], S[nt][1]));
            mx1 = fmaxf(mx1, fmaxf(S[nt][2], S[nt][3]));
        }
        mx0 = fmaxf(mx0, __shfl_xor_sync(0xffffffffu, mx0, 1));
        mx0 = fmaxf(mx0, __shfl_xor_sync(0xffffffffu, mx0, 2));
        mx1 = fmaxf(mx1, __shfl_xor_sync(0xffffffffu, mx1, 1));
        mx1 = fmaxf(mx1, __shfl_xor_sync(0xffffffffu, mx1, 2));
        float m0n = fmaxf(m0, mx0), m1n = fmaxf(m1, mx1);
        float al0 = fexp2((m0 - m0n) * C_EXP);
        float al1 = fexp2((m1 - m1n) * C_EXP);
        float mc0 = m0n * C_EXP, mc1 = m1n * C_EXP;
        l0 *= al0; l1 *= al1;
#pragma unroll
        for (int nt = 0; nt < 8; nt++) {
            float p0 = fexp2(fmaf(S[nt][0], C_EXP, -mc0));
            float p1 = fexp2(fmaf(S[nt][1], C_EXP, -mc0));
            float p2 = fexp2(fmaf(S[nt][2], C_EXP, -mc1));
            float p3 = fexp2(fmaf(S[nt][3], C_EXP, -mc1));
            l0 += p0 + p1; l1 += p2 + p3;
            S[nt][0] = p0; S[nt][1] = p1; S[nt][2] = p2; S[nt][3] = p3;
            O[nt][0] *= al0; O[nt][1] *= al0; O[nt][2] *= al1; O[nt][3] *= al1;
        }
        m0 = m0n; m1 = m1n;

        unsigned ph[4][4], pl[4][4];
#pragma unroll
        for (int tt = 0; tt < 4; tt++) {
            packsplit(S[2*tt][0],   S[2*tt][1],   ph[tt][0], pl[tt][0]);
            packsplit(S[2*tt][2],   S[2*tt][3],   ph[tt][1], pl[tt][1]);
            packsplit(S[2*tt+1][0], S[2*tt+1][1], ph[tt][2], pl[tt][2]);
            packsplit(S[2*tt+1][2], S[2*tt+1][3], ph[tt][3], pl[tt][3]);
        }

        {
            int vlr = lane & 15;
#pragma unroll
            for (int tt = 0; tt < 4; tt++) {
                int rowv = tt * 16 + vlr;
#pragma unroll
                for (int nd = 0; nd < 8; nd++) {
                    unsigned va = sb + 16384 + swz(rowv, nd);
                    unsigned vh0, vh1, vl0, vl1;
                    ldsm2t(vh0, vh1, va);
                    ldsm2t(vl0, vl1, va + 8192);
                    mma16816(O[nd], ph[tt], vh0, vh1);
                    mma16816(O[nd], ph[tt], vl0, vl1);
                    mma16816(O[nd], pl[tt], vh0, vh1);
                }
            }
        }
        __syncthreads();
    }

    l0 += __shfl_xor_sync(0xffffffffu, l0, 1);
    l0 += __shfl_xor_sync(0xffffffffu, l0, 2);
    l1 += __shfl_xor_sync(0xffffffffu, l1, 1);
    l1 += __shfl_xor_sync(0xffffffffu, l1, 2);
    float inv0 = 1.0f / l0, inv1 = 1.0f / l1;

    int s_ = unit / (BB*NH);
    int bh_ = unit % (BB*NH);
    int bi = bh_ / NH, h = bh_ % NH;
    int tok0 = qblk * 128 + R0 + g;
    int tok1 = tok0 + 8;

#pragma unroll
    for (int nd = 0; nd < 8; nd++) {
        int d = nd * 8 + 2 * cc;
        unsigned hw, lw;
        size_t off0 = (size_t)s_ * MD + (size_t)(bi*SEQ + tok0) * DIMC + h*64 + d;
        packsplit(O[nd][0] * inv0, O[nd][1] * inv0, hw, lw);
        *(unsigned*)(g_ohi + off0) = hw;
        *(unsigned*)(g_olo + off0) = lw;
        size_t off1 = (size_t)s_ * MD + (size_t)(bi*SEQ + tok1) * DIMC + h*64 + d;
        packsplit(O[nd][2] * inv1, O[nd][3] * inv1, hw, lw);
        *(unsigned*)(g_ohi + off1) = hw;
        *(unsigned*)(g_olo + off1) = lw;
    }
}

// ---------------- launch -----------------------------------------------------
extern "C" void kernel_launch(void* const* d_in, const int* in_sizes, int n_in,
                              void* d_out, int out_size) {
    const float* x1 = (const float*)d_in[0];
    const float* x2 = (const float*)d_in[1];
    const float* Wq = (const float*)d_in[2];
    const float* bq = (const float*)d_in[3];
    const float* Wk = (const float*)d_in[4];
    const float* bk = (const float*)d_in[5];
    const float* Wv = (const float*)d_in[6];
    const float* bv = (const float*)d_in[7];
    const float* Wo = (const float*)d_in[8];
    const float* bo = (const float*)d_in[9];
    const float* cs = (const float*)d_in[10];

    cudaFuncSetAttribute(qkv_mma,   cudaFuncAttributeMaxDynamicSharedMemorySize, GEMM_SMEM);
    cudaFuncSetAttribute(oproj_mma, cudaFuncAttributeMaxDynamicSharedMemorySize, GEMM_SMEM);
    cudaFuncSetAttribute(attn_mma,  cudaFuncAttributeMaxDynamicSharedMemorySize, AT_SMEM);

    mixcvt_kernel<<<(MTOT * DIMC) / 256, 256>>>(x1, x2, cs);
    wcvt_kernel<<<dim3((DIMC * DIMC) / 256, 4), 256>>>(Wq, Wk, Wv, Wo);

    qkv_mma<<<dim3(6, 32, 6), 256, GEMM_SMEM>>>(bq, bk, bv);

    attn_mma<<<dim3(16, 48), 256, AT_SMEM>>>();

    oproj_mma<<<dim3(6, 32, 2), 256, GEMM_SMEM>>>(bo, (float*)d_out);
}

// round 7
// speedup vs baseline: 1.1323x; 1.0096x over previous
#include <cuda_runtime.h>
#include <cuda_bf16.h>

#define DIMC 768
#define SEQ  2048
#define BB   2
#define NH   12
#define HDD  64
#define MTOT (BB*SEQ)
#define UNITS (2*BB*NH)
#define C_EXP (0.125f * 1.4426950408889634f)
#define MD ((size_t)MTOT*DIMC)
#define WD ((size_t)DIMC*DIMC)

// ---------------- scratch ----------------------------------------------------
__device__ __nv_bfloat16 g_xhi[4*MTOT*DIMC];
__device__ __nv_bfloat16 g_xlo[4*MTOT*DIMC];
__device__ __nv_bfloat16 g_whi[4*DIMC*DIMC];
__device__ __nv_bfloat16 g_wlo[4*DIMC*DIMC];
__device__ __nv_bfloat16 g_qh[UNITS*SEQ*HDD], g_ql[UNITS*SEQ*HDD];
__device__ __nv_bfloat16 g_kh[UNITS*SEQ*HDD], g_kl[UNITS*SEQ*HDD];
__device__ __nv_bfloat16 g_vh[UNITS*SEQ*HDD], g_vl[UNITS*SEQ*HDD];
__device__ __nv_bfloat16 g_ohi[2*MTOT*DIMC];
__device__ __nv_bfloat16 g_olo[2*MTOT*DIMC];

__device__ __forceinline__ float fexp2(float x) {
    float y; asm("ex2.approx.ftz.f32 %0, %1;" : "=f"(y) : "f"(x)); return y;
}
__device__ __forceinline__ void split2(float v, __nv_bfloat16& h, __nv_bfloat16& l) {
    h = __float2bfloat16(v);
    l = __float2bfloat16(v - __bfloat162float(h));
}
__device__ __forceinline__ void packsplit(float a, float b, unsigned& hi, unsigned& lo) {
    union { __nv_bfloat162 v; unsigned u; } h, l;
    h.v = __floats2bfloat162_rn(a, b);
    float2 f = __bfloat1622float2(h.v);
    l.v = __floats2bfloat162_rn(a - f.x, b - f.y);
    hi = h.u; lo = l.u;
}
__device__ __forceinline__ void cp16u(unsigned s, const void* g) {
    asm volatile("cp.async.cg.shared.global [%0], [%1], 16;\n" :: "r"(s), "l"(g));
}
__device__ __forceinline__ void commitg() { asm volatile("cp.async.commit_group;\n"); }
__device__ __forceinline__ void waitg1()  { asm volatile("cp.async.wait_group 1;\n"); }

__device__ __forceinline__ void mma16816(float* d, const unsigned* a, unsigned b0, unsigned b1) {
    asm volatile("mma.sync.aligned.m16n8k16.row.col.f32.bf16.bf16.f32 "
                 "{%0,%1,%2,%3}, {%4,%5,%6,%7}, {%8,%9}, {%0,%1,%2,%3};"
                 : "+f"(d[0]), "+f"(d[1]), "+f"(d[2]), "+f"(d[3])
                 : "r"(a[0]), "r"(a[1]), "r"(a[2]), "r"(a[3]), "r"(b0), "r"(b1));
}
__device__ __forceinline__ void ldsm4(unsigned* r, unsigned a) {
    asm volatile("ldmatrix.sync.aligned.m8n8.x4.shared.b16 {%0,%1,%2,%3}, [%4];"
                 : "=r"(r[0]), "=r"(r[1]), "=r"(r[2]), "=r"(r[3]) : "r"(a));
}
__device__ __forceinline__ void ldsm4t(unsigned* r, unsigned a) {
    asm volatile("ldmatrix.sync.aligned.m8n8.x4.trans.shared.b16 {%0,%1,%2,%3}, [%4];"
                 : "=r"(r[0]), "=r"(r[1]), "=r"(r[2]), "=r"(r[3]) : "r"(a));
}
// swizzled smem chunk offset (chunk = 16B; 8 chunks per 64-bf16 row)
__device__ __forceinline__ unsigned swz(int row, int j) {
    return (unsigned)((row * 8 + (j ^ (row & 7))) << 4);
}

// ---------------- 1) mix + convert activations ------------------------------
__global__ void mixcvt_kernel(const float* __restrict__ x1,
                              const float* __restrict__ x2,
                              const float* __restrict__ sp) {
    int i = blockIdx.x * 256 + threadIdx.x;
    float s = sp[0];
    float a = x1[i], b = x2[i];
    float m0 = (1.0f - s) * a + s * b;
    float m1 = (1.0f - s) * b + s * a;
    split2(a,  g_xhi[i],          g_xlo[i]);
    split2(b,  g_xhi[MD   + i],   g_xlo[MD   + i]);
    split2(m0, g_xhi[2*MD + i],   g_xlo[2*MD + i]);
    split2(m1, g_xhi[3*MD + i],   g_xlo[3*MD + i]);
}

// ---------------- 2) convert weights ----------------------------------------
__global__ void wcvt_kernel(const float* __restrict__ Wq, const float* __restrict__ Wk,
                            const float* __restrict__ Wv, const float* __restrict__ Wo) {
    int i = blockIdx.x * 256 + threadIdx.x;
    int mat = blockIdx.y;
    const float* W = (mat == 0) ? Wq : (mat == 1) ? Wk : (mat == 2) ? Wv : Wo;
    split2(W[i], g_whi[mat*WD + i], g_wlo[mat*WD + i]);
}

// ---------------- GEMM: 128x128 tile, 3-stage, 1 sync per k-block ------------
// K = 768 in 12 blocks of 64. Stage layout (per 64KB stage): Ah @0, Al @16384,
// Bh @32768, Bl @49152; swz()-swizzled 64-bf16 rows.
#define GEMM_SMEM (3 * 65536)

template<bool HEAD_SCATTER>
__device__ __forceinline__ void gemm_body(
    const __nv_bfloat16* __restrict__ Ahi, const __nv_bfloat16* __restrict__ Alo,
    const __nv_bfloat16* __restrict__ Bhi, const __nv_bfloat16* __restrict__ Blo,
    const float* __restrict__ bias,
    float* __restrict__ outf,
    __nv_bfloat16* __restrict__ oh, __nv_bfloat16* __restrict__ ol,
    int m0, int c0, int ubase)
{
    extern __shared__ char smg[];
    unsigned sbase = (unsigned)__cvta_generic_to_shared(smg);
    int t = threadIdx.x, lane = t & 31, w = t >> 5;
    int wm = w & 3, wn = w >> 2;
    int g = lane >> 2, c = lane & 3;
    int mi = lane >> 3, rr = lane & 7;

    const __nv_bfloat16* Ah_g = Ahi + (size_t)m0 * DIMC;
    const __nv_bfloat16* Al_g = Alo + (size_t)m0 * DIMC;
    const __nv_bfloat16* Bh_g = Bhi + (size_t)c0 * DIMC;
    const __nv_bfloat16* Bl_g = Blo + (size_t)c0 * DIMC;

    float acc[2][8][4];
#pragma unroll
    for (int mt = 0; mt < 2; mt++)
#pragma unroll
        for (int nt = 0; nt < 8; nt++)
#pragma unroll
            for (int j = 0; j < 4; j++) acc[mt][nt][j] = 0.0f;

    int lrow = t >> 1, lj0 = (t & 1) * 4;

    // prologue: kb0 -> stage 0 (G0), kb1 -> stage 1 (G1)
#pragma unroll
    for (int s = 0; s < 2; s++) {
        unsigned st = sbase + s * 65536;
#pragma unroll
        for (int jj = 0; jj < 4; jj++) {
            int j = lj0 + jj;
            unsigned so = swz(lrow, j);
            size_t go = (size_t)lrow * DIMC + s * 64 + j * 8;
            cp16u(st + so,         Ah_g + go);
            cp16u(st + 16384 + so, Al_g + go);
            cp16u(st + 32768 + so, Bh_g + go);
            cp16u(st + 49152 + so, Bl_g + go);
        }
        commitg();
    }

    for (int kb = 0; kb < 12; kb++) {
        waitg1();
        __syncthreads();
        if (kb < 10) {
            unsigned st = sbase + (unsigned)((kb + 2) % 3) * 65536;
#pragma unroll
            for (int jj = 0; jj < 4; jj++) {
                int j = lj0 + jj;
                unsigned so = swz(lrow, j);
                size_t go = (size_t)lrow * DIMC + (kb + 2) * 64 + j * 8;
                cp16u(st + so,         Ah_g + go);
                cp16u(st + 16384 + so, Al_g + go);
                cp16u(st + 32768 + so, Bh_g + go);
                cp16u(st + 49152 + so, Bl_g + go);
            }
        }
        commitg();

        unsigned sb = sbase + (unsigned)(kb % 3) * 65536;

#pragma unroll
        for (int kk = 0; kk < 4; kk++) {
            int rowa = wm * 32 + (mi & 1) * 8 + rr;
            int jc = kk * 2 + (mi >> 1);
            unsigned ah0[4], ah1[4], al0[4], al1[4];
            ldsm4(ah0, sb + swz(rowa, jc));
            ldsm4(ah1, sb + swz(rowa + 16, jc));
            ldsm4(al0, sb + 16384 + swz(rowa, jc));
            ldsm4(al1, sb + 16384 + swz(rowa + 16, jc));
#pragma unroll
            for (int nt2 = 0; nt2 < 4; nt2++) {
                int rowb = wn * 64 + nt2 * 16 + (mi >> 1) * 8 + rr;
                int jb = kk * 2 + (mi & 1);
                unsigned bh[4], bl[4];
                ldsm4(bh, sb + 32768 + swz(rowb, jb));
                ldsm4(bl, sb + 49152 + swz(rowb, jb));
                int n0 = nt2 * 2, n1 = nt2 * 2 + 1;
                mma16816(acc[0][n0], ah0, bh[0], bh[1]);
                mma16816(acc[0][n1], ah0, bh[2], bh[3]);
                mma16816(acc[1][n0], ah1, bh[0], bh[1]);
                mma16816(acc[1][n1], ah1, bh[2], bh[3]);
                mma16816(acc[0][n0], ah0, bl[0], bl[1]);
                mma16816(acc[0][n1], ah0, bl[2], bl[3]);
                mma16816(acc[1][n0], ah1, bl[0], bl[1]);
                mma16816(acc[1][n1], ah1, bl[2], bl[3]);
                mma16816(acc[0][n0], al0, bh[0], bh[1]);
                mma16816(acc[0][n1], al0, bh[2], bh[3]);
                mma16816(acc[1][n0], al1, bh[0], bh[1]);
                mma16816(acc[1][n1], al1, bh[2], bh[3]);
            }
        }
    }

    // ---- epilogue ----
#pragma unroll
    for (int mt = 0; mt < 2; mt++) {
#pragma unroll
        for (int nt = 0; nt < 8; nt++) {
            int r0 = m0 + wm * 32 + mt * 16 + g;
            int col = c0 + wn * 64 + nt * 8 + 2 * c;
            float bb0 = bias[col], bb1 = bias[col + 1];
            float* A4 = acc[mt][nt];
            if (HEAD_SCATTER) {
                int h = col >> 6, d = col & 63;
                {
                    int bi = r0 >> 11, n = r0 & 2047;
                    size_t off = (((size_t)(ubase + bi*NH + h))*SEQ + n)*HDD + d;
                    unsigned hw, lw; packsplit(A4[0] + bb0, A4[1] + bb1, hw, lw);
                    *(unsigned*)(oh + off) = hw;
                    *(unsigned*)(ol + off) = lw;
                }
                {
                    int r1 = r0 + 8;
                    int bi = r1 >> 11, n = r1 & 2047;
                    size_t off = (((size_t)(ubase + bi*NH + h))*SEQ + n)*HDD + d;
                    unsigned hw, lw; packsplit(A4[2] + bb0, A4[3] + bb1, hw, lw);
                    *(unsigned*)(oh + off) = hw;
                    *(unsigned*)(ol + off) = lw;
                }
            } else {
                float2 v0 = make_float2(A4[0] + bb0, A4[1] + bb1);
                float2 v1 = make_float2(A4[2] + bb0, A4[3] + bb1);
                *(float2*)&outf[(size_t)r0 * DIMC + col]     = v0;
                *(float2*)&outf[(size_t)(r0+8) * DIMC + col] = v1;
            }
        }
    }
}

// ---------------- 3) fused QKV projection -----------------------------------
__global__ __launch_bounds__(256, 1)
void qkv_mma(const float* __restrict__ bq, const float* __restrict__ bk,
             const float* __restrict__ bv) {
    int z = blockIdx.z, s = z / 3, which = z % 3;
    int amat = (which == 1) ? (2 + s) : s;
    const __nv_bfloat16* Ahi = g_xhi + (size_t)amat * MD;
    const __nv_bfloat16* Alo = g_xlo + (size_t)amat * MD;
    const __nv_bfloat16* Bhi = g_whi + (size_t)which * WD;
    const __nv_bfloat16* Blo = g_wlo + (size_t)which * WD;
    const float* bias = (which == 0) ? bq : (which == 1) ? bk : bv;
    __nv_bfloat16* oh = (which == 0) ? g_qh : (which == 1) ? g_kh : g_vh;
    __nv_bfloat16* ol = (which == 0) ? g_ql : (which == 1) ? g_kl : g_vl;
    gemm_body<true>(Ahi, Alo, Bhi, Blo, bias, nullptr, oh, ol,
                    blockIdx.y * 128, blockIdx.x * 128, s * BB * NH);
}

// ---------------- 5) output projection --------------------------------------
__global__ __launch_bounds__(256, 1)
void oproj_mma(const float* __restrict__ bo, float* __restrict__ out) {
    int s = blockIdx.z;
    gemm_body<false>(g_ohi + (size_t)s * MD, g_olo + (size_t)s * MD,
                     g_whi + 3 * WD, g_wlo + 3 * WD, bo, out + (size_t)s * MD,
                     nullptr, nullptr, blockIdx.y * 128, blockIdx.x * 128, 0);
}

// ---------------- 4) flash attention: 8 warps/128q, 3-stage, 1 sync/iter ----
// smem: stage s at s*32768 (Kh 0, Kl 8K, Vh 16K, Vl 24K); Q at 98304
// (Qh 16KB, Ql 16KB @114688). Total 131072 bytes.
#define AT_SMEM 131072

__global__ __launch_bounds__(256, 1)
void attn_mma() {
    extern __shared__ char smca[];
    unsigned sbase = (unsigned)__cvta_generic_to_shared(smca);
    int t = threadIdx.x, lane = t & 31, w = t >> 5;
    int g = lane >> 2, cc = lane & 3;
    int unit = blockIdx.y, qblk = blockIdx.x;

    const __nv_bfloat16* Qh_g = g_qh + (size_t)unit*SEQ*HDD + (size_t)qblk*128*HDD;
    const __nv_bfloat16* Ql_g = g_ql + (size_t)unit*SEQ*HDD + (size_t)qblk*128*HDD;
    const __nv_bfloat16* Kh_g = g_kh + (size_t)unit*SEQ*HDD;
    const __nv_bfloat16* Kl_g = g_kl + (size_t)unit*SEQ*HDD;
    const __nv_bfloat16* Vh_g = g_vh + (size_t)unit*SEQ*HDD;
    const __nv_bfloat16* Vl_g = g_vl + (size_t)unit*SEQ*HDD;

    int krow = t >> 2, kj0 = (t & 3) * 2;

    // ---- G0: Q (hi+lo) + KV tile 0 -> stage 0 ----
    {
        int row = t >> 1, j0 = (t & 1) * 4;
#pragma unroll
        for (int jj = 0; jj < 4; jj++) {
            int j = j0 + jj;
            cp16u(sbase + 98304  + swz(row, j), Qh_g + row*64 + j*8);
            cp16u(sbase + 114688 + swz(row, j), Ql_g + row*64 + j*8);
        }
#pragma unroll
        for (int jj = 0; jj < 2; jj++) {
            int j = kj0 + jj;
            unsigned so = swz(krow, j);
            size_t go = (size_t)krow * 64 + j * 8;
            cp16u(sbase + so,         Kh_g + go);
            cp16u(sbase + 8192  + so, Kl_g + go);
            cp16u(sbase + 16384 + so, Vh_g + go);
            cp16u(sbase + 24576 + so, Vl_g + go);
        }
    }
    commitg();
    // ---- G1: KV tile 1 -> stage 1 ----
#pragma unroll
    for (int jj = 0; jj < 2; jj++) {
        int j = kj0 + jj;
        unsigned so = swz(krow, j);
        size_t go = (size_t)(64 + krow) * 64 + j * 8;
        cp16u(sbase + 32768 + so, Kh_g + go);
        cp16u(sbase + 40960 + so, Kl_g + go);
        cp16u(sbase + 49152 + so, Vh_g + go);
        cp16u(sbase + 57344 + so, Vl_g + go);
    }
    commitg();
    waitg1();          // G0 done (Q + tile0)
    __syncthreads();

    // ---- Q fragments to registers (Q region is never overwritten) ----
    unsigned qh[4][4], ql[4][4];
    int R0 = w * 16;
    {
        int mi = lane >> 3, rr = lane & 7;
#pragma unroll
        for (int kk = 0; kk < 4; kk++) {
            int rowq = R0 + (mi & 1) * 8 + rr;
            int jc = kk * 2 + (mi >> 1);
            unsigned a = sbase + 98304 + swz(rowq, jc);
            ldsm4(qh[kk], a);
            ldsm4(ql[kk], a + 16384);
        }
    }

    float O[8][4];
#pragma unroll
    for (int nt = 0; nt < 8; nt++)
#pragma unroll
        for (int j = 0; j < 4; j++) O[nt][j] = 0.0f;
    float m0 = -1e30f, m1 = -1e30f, l0 = 0.0f, l1 = 0.0f;

    for (int kt = 0; kt < 32; kt++) {
        waitg1();              // stage kt's group complete
        __syncthreads();       // all warps done with stage (kt+2)%3 == (kt-1)%3
        if (kt < 30) {
            unsigned sb2 = sbase + (unsigned)((kt + 2) % 3) * 32768;
#pragma unroll
            for (int jj = 0; jj < 2; jj++) {
                int j = kj0 + jj;
                unsigned so = swz(krow, j);
                size_t go = (size_t)((kt + 2) * 64 + krow) * 64 + j * 8;
                cp16u(sb2 + so,         Kh_g + go);
                cp16u(sb2 + 8192  + so, Kl_g + go);
                cp16u(sb2 + 16384 + so, Vh_g + go);
                cp16u(sb2 + 24576 + so, Vl_g + go);
            }
        }
        commitg();

        unsigned sb = sbase + (unsigned)(kt % 3) * 32768;

        // ---- S = Q K^T (3-mma hi/lo; x4 K loads cover two n8 frags) ----
        float S[8][4];
#pragma unroll
        for (int nt = 0; nt < 8; nt++)
#pragma unroll
            for (int j = 0; j < 4; j++) S[nt][j] = 0.0f;

        {
            int rr = lane & 7, q2 = lane >> 3;        // q2 = 0..3
            int rowbase = (q2 >> 1) * 8 + rr;          // +8 for second matrix pair
            int hf = q2 & 1;
#pragma unroll
            for (int ntp = 0; ntp < 4; ntp++) {
                int rowk = ntp * 16 + rowbase;
#pragma unroll
                for (int kk = 0; kk < 4; kk++) {
                    unsigned ka = sb + swz(rowk, kk * 2 + hf);
                    unsigned bh[4], bl[4];
                    ldsm4(bh, ka);
                    ldsm4(bl, ka + 8192);
                    int n0 = ntp * 2, n1 = ntp * 2 + 1;
                    mma16816(S[n0], qh[kk], bh[0], bh[1]);
                    mma16816(S[n1], qh[kk], bh[2], bh[3]);
                    mma16816(S[n0], qh[kk], bl[0], bl[1]);
                    mma16816(S[n1], qh[kk], bl[2], bl[3]);
                    mma16816(S[n0], ql[kk], bh[0], bh[1]);
                    mma16816(S[n1], ql[kk], bh[2], bh[3]);
                }
            }
        }

        // ---- online softmax ----
        float mx0 = -1e30f, mx1 = -1e30f;
#pragma unroll
        for (int nt = 0; nt < 8; nt++) {
            mx0 = fmaxf(mx0, fmaxf(S[nt][0], S[nt][1]));
            mx1 = fmaxf(mx1, fmaxf(S[nt][2], S[nt][3]));
        }
        mx0 = fmaxf(mx0, __shfl_xor_sync(0xffffffffu, mx0, 1));
        mx0 = fmaxf(mx0, __shfl_xor_sync(0xffffffffu, mx0, 2));
        mx1 = fmaxf(mx1, __shfl_xor_sync(0xffffffffu, mx1, 1));
        mx1 = fmaxf(mx1, __shfl_xor_sync(0xffffffffu, mx1, 2));
        float m0n = fmaxf(m0, mx0), m1n = fmaxf(m1, mx1);
        float al0 = fexp2((m0 - m0n) * C_EXP);
        float al1 = fexp2((m1 - m1n) * C_EXP);
        float mc0 = m0n * C_EXP, mc1 = m1n * C_EXP;
        l0 *= al0; l1 *= al1;
#pragma unroll
        for (int nt = 0; nt < 8; nt++) {
            float p0 = fexp2(fmaf(S[nt][0], C_EXP, -mc0));
            float p1 = fexp2(fmaf(S[nt][1], C_EXP, -mc0));
            float p2 = fexp2(fmaf(S[nt][2], C_EXP, -mc1));
            float p3 = fexp2(fmaf(S[nt][3], C_EXP, -mc1));
            l0 += p0 + p1; l1 += p2 + p3;
            S[nt][0] = p0; S[nt][1] = p1; S[nt][2] = p2; S[nt][3] = p3;
            O[nt][0] *= al0; O[nt][1] *= al0; O[nt][2] *= al1; O[nt][3] *= al1;
        }
        m0 = m0n; m1 = m1n;

        // ---- pack P into A-fragments (hi/lo) ----
        unsigned ph[4][4], pl[4][4];
#pragma unroll
        for (int tt = 0; tt < 4; tt++) {
            packsplit(S[2*tt][0],   S[2*tt][1],   ph[tt][0], pl[tt][0]);
            packsplit(S[2*tt][2],   S[2*tt][3],   ph[tt][1], pl[tt][1]);
            packsplit(S[2*tt+1][0], S[2*tt+1][1], ph[tt][2], pl[tt][2]);
            packsplit(S[2*tt+1][2], S[2*tt+1][3], ph[tt][3], pl[tt][3]);
        }

        // ---- O += P V (x4-trans V loads cover two d8 frags) ----
        {
            int vlr = lane & 15, vh2 = lane >> 4;     // vh2 = 0..1
#pragma unroll
            for (int tt = 0; tt < 4; tt++) {
                int rowv = tt * 16 + vlr;
#pragma unroll
                for (int ndp = 0; ndp < 4; ndp++) {
                    unsigned va = sb + 16384 + swz(rowv, ndp * 2 + vh2);
                    unsigned vh[4], vl[4];
                    ldsm4t(vh, va);
                    ldsm4t(vl, va + 8192);
                    int n0 = ndp * 2, n1 = ndp * 2 + 1;
                    mma16816(O[n0], ph[tt], vh[0], vh[1]);
                    mma16816(O[n1], ph[tt], vh[2], vh[3]);
                    mma16816(O[n0], ph[tt], vl[0], vl[1]);
                    mma16816(O[n1], ph[tt], vl[2], vl[3]);
                    mma16816(O[n0], pl[tt], vh[0], vh[1]);
                    mma16816(O[n1], pl[tt], vh[2], vh[3]);
                }
            }
        }
    }

    // ---- epilogue ----
    l0 += __shfl_xor_sync(0xffffffffu, l0, 1);
    l0 += __shfl_xor_sync(0xffffffffu, l0, 2);
    l1 += __shfl_xor_sync(0xffffffffu, l1, 1);
    l1 += __shfl_xor_sync(0xffffffffu, l1, 2);
    float inv0 = 1.0f / l0, inv1 = 1.0f / l1;

    int s_ = unit / (BB*NH);
    int bh_ = unit % (BB*NH);
    int bi = bh_ / NH, h = bh_ % NH;
    int tok0 = qblk * 128 + R0 + g;
    int tok1 = tok0 + 8;

#pragma unroll
    for (int nd = 0; nd < 8; nd++) {
        int d = nd * 8 + 2 * cc;
        unsigned hw, lw;
        size_t off0 = (size_t)s_ * MD + (size_t)(bi*SEQ + tok0) * DIMC + h*64 + d;
        packsplit(O[nd][0] * inv0, O[nd][1] * inv0, hw, lw);
        *(unsigned*)(g_ohi + off0) = hw;
        *(unsigned*)(g_olo + off0) = lw;
        size_t off1 = (size_t)s_ * MD + (size_t)(bi*SEQ + tok1) * DIMC + h*64 + d;
        packsplit(O[nd][2] * inv1, O[nd][3] * inv1, hw, lw);
        *(unsigned*)(g_ohi + off1) = hw;
        *(unsigned*)(g_olo + off1) = lw;
    }
}

// ---------------- launch -----------------------------------------------------
extern "C" void kernel_launch(void* const* d_in, const int* in_sizes, int n_in,
                              void* d_out, int out_size) {
    const float* x1 = (const float*)d_in[0];
    const float* x2 = (const float*)d_in[1];
    const float* Wq = (const float*)d_in[2];
    const float* bq = (const float*)d_in[3];
    const float* Wk = (const float*)d_in[4];
    const float* bk = (const float*)d_in[5];
    const float* Wv = (const float*)d_in[6];
    const float* bv = (const float*)d_in[7];
    const float* Wo = (const float*)d_in[8];
    const float* bo = (const float*)d_in[9];
    const float* cs = (const float*)d_in[10];

    cudaFuncSetAttribute(qkv_mma,   cudaFuncAttributeMaxDynamicSharedMemorySize, GEMM_SMEM);
    cudaFuncSetAttribute(oproj_mma, cudaFuncAttributeMaxDynamicSharedMemorySize, GEMM_SMEM);
    cudaFuncSetAttribute(attn_mma,  cudaFuncAttributeMaxDynamicSharedMemorySize, AT_SMEM);

    mixcvt_kernel<<<(MTOT * DIMC) / 256, 256>>>(x1, x2, cs);
    wcvt_kernel<<<dim3((DIMC * DIMC) / 256, 4), 256>>>(Wq, Wk, Wv, Wo);

    qkv_mma<<<dim3(6, 32, 6), 256, GEMM_SMEM>>>(bq, bk, bv);

    attn_mma<<<dim3(16, 48), 256, AT_SMEM>>>();

    oproj_mma<<<dim3(6, 32, 2), 256, GEMM_SMEM>>>(bo, (float*)d_out);
}

// round 8
// speedup vs baseline: 1.2035x; 1.0629x over previous
#include <cuda_runtime.h>
#include <cuda_bf16.h>
#include <cuda.h>

#define DIMC 768
#define SEQ  2048
#define BB   2
#define NH   12
#define HDD  64
#define MTOT (BB*SEQ)
#define UNITS (2*BB*NH)
#define C_EXP (0.125f * 1.4426950408889634f)
#define MD ((size_t)MTOT*DIMC)
#define WD ((size_t)DIMC*DIMC)

// ---------------- scratch ----------------------------------------------------
__device__ __nv_bfloat16 g_xhi[4*MTOT*DIMC];
__device__ __nv_bfloat16 g_xlo[4*MTOT*DIMC];
__device__ __nv_bfloat16 g_whi[4*DIMC*DIMC];
__device__ __nv_bfloat16 g_wlo[4*DIMC*DIMC];
__device__ __nv_bfloat16 g_qh[UNITS*SEQ*HDD], g_ql[UNITS*SEQ*HDD];
__device__ __nv_bfloat16 g_kh[UNITS*SEQ*HDD], g_kl[UNITS*SEQ*HDD];
__device__ __nv_bfloat16 g_vh[UNITS*SEQ*HDD], g_vl[UNITS*SEQ*HDD];
__device__ __nv_bfloat16 g_ohi[2*MTOT*DIMC];
__device__ __nv_bfloat16 g_olo[2*MTOT*DIMC];

__device__ __forceinline__ float fexp2(float x) {
    float y; asm("ex2.approx.ftz.f32 %0, %1;" : "=f"(y) : "f"(x)); return y;
}
__device__ __forceinline__ void split2(float v, __nv_bfloat16& h, __nv_bfloat16& l) {
    h = __float2bfloat16(v);
    l = __float2bfloat16(v - __bfloat162float(h));
}
__device__ __forceinline__ void packsplit(float a, float b, unsigned& hi, unsigned& lo) {
    union { __nv_bfloat162 v; unsigned u; } h, l;
    h.v = __floats2bfloat162_rn(a, b);
    float2 f = __bfloat1622float2(h.v);
    l.v = __floats2bfloat162_rn(a - f.x, b - f.y);
    hi = h.u; lo = l.u;
}
__device__ __forceinline__ void cp16u(unsigned s, const void* g) {
    asm volatile("cp.async.cg.shared.global [%0], [%1], 16;\n" :: "r"(s), "l"(g));
}
__device__ __forceinline__ void commitg() { asm volatile("cp.async.commit_group;\n"); }
__device__ __forceinline__ void waitg1()  { asm volatile("cp.async.wait_group 1;\n"); }
__device__ __forceinline__ void waitg0()  { asm volatile("cp.async.wait_group 0;\n"); }

__device__ __forceinline__ void mma16816(float* d, const unsigned* a, unsigned b0, unsigned b1) {
    asm volatile("mma.sync.aligned.m16n8k16.row.col.f32.bf16.bf16.f32 "
                 "{%0,%1,%2,%3}, {%4,%5,%6,%7}, {%8,%9}, {%0,%1,%2,%3};"
                 : "+f"(d[0]), "+f"(d[1]), "+f"(d[2]), "+f"(d[3])
                 : "r"(a[0]), "r"(a[1]), "r"(a[2]), "r"(a[3]), "r"(b0), "r"(b1));
}
__device__ __forceinline__ void ldsm4(unsigned* r, unsigned a) {
    asm volatile("ldmatrix.sync.aligned.m8n8.x4.shared.b16 {%0,%1,%2,%3}, [%4];"
                 : "=r"(r[0]), "=r"(r[1]), "=r"(r[2]), "=r"(r[3]) : "r"(a));
}
__device__ __forceinline__ void ldsm4t(unsigned* r, unsigned a) {
    asm volatile("ldmatrix.sync.aligned.m8n8.x4.trans.shared.b16 {%0,%1,%2,%3}, [%4];"
                 : "=r"(r[0]), "=r"(r[1]), "=r"(r[2]), "=r"(r[3]) : "r"(a));
}
// swizzled smem chunk offset (chunk = 16B; 8 chunks per 64-bf16 row)
// NOTE: identical to TMA CU_TENSOR_MAP_SWIZZLE_128B for 128B rows.
__device__ __forceinline__ unsigned swz(int row, int j) {
    return (unsigned)((row * 8 + (j ^ (row & 7))) << 4);
}

// ---------------- mbarrier / TMA primitives ----------------------------------
__device__ __forceinline__ void mbar_init(unsigned a, unsigned cnt) {
    asm volatile("mbarrier.init.shared.b64 [%0], %1;" :: "r"(a), "r"(cnt) : "memory");
}
__device__ __forceinline__ void mbar_expect_tx(unsigned a, unsigned bytes) {
    asm volatile("mbarrier.arrive.expect_tx.shared.b64 _, [%0], %1;" :: "r"(a), "r"(bytes) : "memory");
}
__device__ __forceinline__ void mbar_arrive(unsigned a) {
    asm volatile("mbarrier.arrive.shared.b64 _, [%0];" :: "r"(a) : "memory");
}
__device__ __forceinline__ void mbar_wait(unsigned a, unsigned parity) {
    asm volatile(
        "{\n\t.reg .pred P;\n\t"
        "WL_%=:\n\t"
        "mbarrier.try_wait.parity.acquire.cta.shared::cta.b64 P, [%0], %1, 0x989680;\n\t"
        "@P bra.uni WD_%=;\n\t"
        "bra.uni WL_%=;\n\t"
        "WD_%=:\n\t}"
        :: "r"(a), "r"(parity) : "memory");
}
__device__ __forceinline__ void tma2d(unsigned dst, const void* map, int x, int y, unsigned mbar) {
    asm volatile("cp.async.bulk.tensor.2d.shared::cta.global.tile.mbarrier::complete_tx::bytes "
                 "[%0], [%1, {%2, %3}], [%4];"
                 :: "r"(dst), "l"(map), "r"(x), "r"(y), "r"(mbar) : "memory");
}

// ---------------- 1) mix + convert activations ------------------------------
__global__ void mixcvt_kernel(const float* __restrict__ x1,
                              const float* __restrict__ x2,
                              const float* __restrict__ sp) {
    int i = blockIdx.x * 256 + threadIdx.x;
    float s = sp[0];
    float a = x1[i], b = x2[i];
    float m0 = (1.0f - s) * a + s * b;
    float m1 = (1.0f - s) * b + s * a;
    split2(a,  g_xhi[i],          g_xlo[i]);
    split2(b,  g_xhi[MD   + i],   g_xlo[MD   + i]);
    split2(m0, g_xhi[2*MD + i],   g_xlo[2*MD + i]);
    split2(m1, g_xhi[3*MD + i],   g_xlo[3*MD + i]);
}

// ---------------- 2) convert weights ----------------------------------------
__global__ void wcvt_kernel(const float* __restrict__ Wq, const float* __restrict__ Wk,
                            const float* __restrict__ Wv, const float* __restrict__ Wo) {
    int i = blockIdx.x * 256 + threadIdx.x;
    int mat = blockIdx.y;
    const float* W = (mat == 0) ? Wq : (mat == 1) ? Wk : (mat == 2) ? Wv : Wo;
    split2(W[i], g_whi[mat*WD + i], g_wlo[mat*WD + i]);
}

// ---------------- GEMM: 128x128 tile, 3-stage, 1 sync per k-block ------------
#define GEMM_SMEM (3 * 65536)

template<bool HEAD_SCATTER>
__device__ __forceinline__ void gemm_body(
    const __nv_bfloat16* __restrict__ Ahi, const __nv_bfloat16* __restrict__ Alo,
    const __nv_bfloat16* __restrict__ Bhi, const __nv_bfloat16* __restrict__ Blo,
    const float* __restrict__ bias,
    float* __restrict__ outf,
    __nv_bfloat16* __restrict__ oh, __nv_bfloat16* __restrict__ ol,
    int m0, int c0, int ubase)
{
    extern __shared__ char smg[];
    unsigned sbase = (unsigned)__cvta_generic_to_shared(smg);
    int t = threadIdx.x, lane = t & 31, w = t >> 5;
    int wm = w & 3, wn = w >> 2;
    int g = lane >> 2, c = lane & 3;
    int mi = lane >> 3, rr = lane & 7;

    const __nv_bfloat16* Ah_g = Ahi + (size_t)m0 * DIMC;
    const __nv_bfloat16* Al_g = Alo + (size_t)m0 * DIMC;
    const __nv_bfloat16* Bh_g = Bhi + (size_t)c0 * DIMC;
    const __nv_bfloat16* Bl_g = Blo + (size_t)c0 * DIMC;

    float acc[2][8][4];
#pragma unroll
    for (int mt = 0; mt < 2; mt++)
#pragma unroll
        for (int nt = 0; nt < 8; nt++)
#pragma unroll
            for (int j = 0; j < 4; j++) acc[mt][nt][j] = 0.0f;

    int lrow = t >> 1, lj0 = (t & 1) * 4;

#pragma unroll
    for (int s = 0; s < 2; s++) {
        unsigned st = sbase + s * 65536;
#pragma unroll
        for (int jj = 0; jj < 4; jj++) {
            int j = lj0 + jj;
            unsigned so = swz(lrow, j);
            size_t go = (size_t)lrow * DIMC + s * 64 + j * 8;
            cp16u(st + so,         Ah_g + go);
            cp16u(st + 16384 + so, Al_g + go);
            cp16u(st + 32768 + so, Bh_g + go);
            cp16u(st + 49152 + so, Bl_g + go);
        }
        commitg();
    }

    for (int kb = 0; kb < 12; kb++) {
        waitg1();
        __syncthreads();
        if (kb < 10) {
            unsigned st = sbase + (unsigned)((kb + 2) % 3) * 65536;
#pragma unroll
            for (int jj = 0; jj < 4; jj++) {
                int j = lj0 + jj;
                unsigned so = swz(lrow, j);
                size_t go = (size_t)lrow * DIMC + (kb + 2) * 64 + j * 8;
                cp16u(st + so,         Ah_g + go);
                cp16u(st + 16384 + so, Al_g + go);
                cp16u(st + 32768 + so, Bh_g + go);
                cp16u(st + 49152 + so, Bl_g + go);
            }
        }
        commitg();

        unsigned sb = sbase + (unsigned)(kb % 3) * 65536;

#pragma unroll
        for (int kk = 0; kk < 4; kk++) {
            int rowa = wm * 32 + (mi & 1) * 8 + rr;
            int jc = kk * 2 + (mi >> 1);
            unsigned ah0[4], ah1[4], al0[4], al1[4];
            ldsm4(ah0, sb + swz(rowa, jc));
            ldsm4(ah1, sb + swz(rowa + 16, jc));
            ldsm4(al0, sb + 16384 + swz(rowa, jc));
            ldsm4(al1, sb + 16384 + swz(rowa + 16, jc));
#pragma unroll
            for (int nt2 = 0; nt2 < 4; nt2++) {
                int rowb = wn * 64 + nt2 * 16 + (mi >> 1) * 8 + rr;
                int jb = kk * 2 + (mi & 1);
                unsigned bh[4], bl[4];
                ldsm4(bh, sb + 32768 + swz(rowb, jb));
                ldsm4(bl, sb + 49152 + swz(rowb, jb));
                int n0 = nt2 * 2, n1 = nt2 * 2 + 1;
                mma16816(acc[0][n0], ah0, bh[0], bh[1]);
                mma16816(acc[0][n1], ah0, bh[2], bh[3]);
                mma16816(acc[1][n0], ah1, bh[0], bh[1]);
                mma16816(acc[1][n1], ah1, bh[2], bh[3]);
                mma16816(acc[0][n0], ah0, bl[0], bl[1]);
                mma16816(acc[0][n1], ah0, bl[2], bl[3]);
                mma16816(acc[1][n0], ah1, bl[0], bl[1]);
                mma16816(acc[1][n1], ah1, bl[2], bl[3]);
                mma16816(acc[0][n0], al0, bh[0], bh[1]);
                mma16816(acc[0][n1], al0, bh[2], bh[3]);
                mma16816(acc[1][n0], al1, bh[0], bh[1]);
                mma16816(acc[1][n1], al1, bh[2], bh[3]);
            }
        }
    }

#pragma unroll
    for (int mt = 0; mt < 2; mt++) {
#pragma unroll
        for (int nt = 0; nt < 8; nt++) {
            int r0 = m0 + wm * 32 + mt * 16 + g;
            int col = c0 + wn * 64 + nt * 8 + 2 * c;
            float bb0 = bias[col], bb1 = bias[col + 1];
            float* A4 = acc[mt][nt];
            if (HEAD_SCATTER) {
                int h = col >> 6, d = col & 63;
                {
                    int bi = r0 >> 11, n = r0 & 2047;
                    size_t off = (((size_t)(ubase + bi*NH + h))*SEQ + n)*HDD + d;
                    unsigned hw, lw; packsplit(A4[0] + bb0, A4[1] + bb1, hw, lw);
                    *(unsigned*)(oh + off) = hw;
                    *(unsigned*)(ol + off) = lw;
                }
                {
                    int r1 = r0 + 8;
                    int bi = r1 >> 11, n = r1 & 2047;
                    size_t off = (((size_t)(ubase + bi*NH + h))*SEQ + n)*HDD + d;
                    unsigned hw, lw; packsplit(A4[2] + bb0, A4[3] + bb1, hw, lw);
                    *(unsigned*)(oh + off) = hw;
                    *(unsigned*)(ol + off) = lw;
                }
            } else {
                float2 v0 = make_float2(A4[0] + bb0, A4[1] + bb1);
                float2 v1 = make_float2(A4[2] + bb0, A4[3] + bb1);
                *(float2*)&outf[(size_t)r0 * DIMC + col]     = v0;
                *(float2*)&outf[(size_t)(r0+8) * DIMC + col] = v1;
            }
        }
    }
}

// ---------------- 3) fused QKV projection -----------------------------------
__global__ __launch_bounds__(256, 1)
void qkv_mma(const float* __restrict__ bq, const float* __restrict__ bk,
             const float* __restrict__ bv) {
    int z = blockIdx.z, s = z / 3, which = z % 3;
    int amat = (which == 1) ? (2 + s) : s;
    const __nv_bfloat16* Ahi = g_xhi + (size_t)amat * MD;
    const __nv_bfloat16* Alo = g_xlo + (size_t)amat * MD;
    const __nv_bfloat16* Bhi = g_whi + (size_t)which * WD;
    const __nv_bfloat16* Blo = g_wlo + (size_t)which * WD;
    const float* bias = (which == 0) ? bq : (which == 1) ? bk : bv;
    __nv_bfloat16* oh = (which == 0) ? g_qh : (which == 1) ? g_kh : g_vh;
    __nv_bfloat16* ol = (which == 0) ? g_ql : (which == 1) ? g_kl : g_vl;
    gemm_body<true>(Ahi, Alo, Bhi, Blo, bias, nullptr, oh, ol,
                    blockIdx.y * 128, blockIdx.x * 128, s * BB * NH);
}

// ---------------- 5) output projection --------------------------------------
__global__ __launch_bounds__(256, 1)
void oproj_mma(const float* __restrict__ bo, float* __restrict__ out) {
    int s = blockIdx.z;
    gemm_body<false>(g_ohi + (size_t)s * MD, g_olo + (size_t)s * MD,
                     g_whi + 3 * WD, g_wlo + 3 * WD, bo, out + (size_t)s * MD,
                     nullptr, nullptr, blockIdx.y * 128, blockIdx.x * 128, 0);
}

// ---------------- 4) flash attention: TMA + mbarrier, no loop barriers -------
// smem: KV stage s at s*32768 (Kh 0, Kl 8K, Vh 16K, Vl 24K);
// Q at 98304 (Qh 16KB) / 114688 (Ql 16KB); mbarriers at 131072:
// full[0..2] @ +0,+8,+16 ; empty[0..2] @ +24,+32,+40.
#define AT_SMEM (131072 + 64)

__global__ __launch_bounds__(256, 1)
void attn_mma(const __grid_constant__ CUtensorMap mKh,
              const __grid_constant__ CUtensorMap mKl,
              const __grid_constant__ CUtensorMap mVh,
              const __grid_constant__ CUtensorMap mVl) {
    extern __shared__ char smca[];
    unsigned sbase = (unsigned)__cvta_generic_to_shared(smca);
    int t = threadIdx.x, lane = t & 31, w = t >> 5;
    int g = lane >> 2, cc = lane & 3;
    int unit = blockIdx.y, qblk = blockIdx.x;
    int ybase = unit * SEQ;

    const __nv_bfloat16* Qh_g = g_qh + (size_t)unit*SEQ*HDD + (size_t)qblk*128*HDD;
    const __nv_bfloat16* Ql_g = g_ql + (size_t)unit*SEQ*HDD + (size_t)qblk*128*HDD;

    unsigned mb = sbase + 131072;

    // ---- init mbarriers ----
    if (t == 0) {
#pragma unroll
        for (int s = 0; s < 3; s++) {
            mbar_init(mb + s * 8, 1);        // full: 1 expect_tx arrive
            mbar_init(mb + 24 + s * 8, 8);   // empty: 8 warp arrivals
        }
    }

    // ---- Q (hi+lo) via cp.async ----
    {
        int row = t >> 1, j0 = (t & 1) * 4;
#pragma unroll
        for (int jj = 0; jj < 4; jj++) {
            int j = j0 + jj;
            cp16u(sbase + 98304  + swz(row, j), Qh_g + row*64 + j*8);
            cp16u(sbase + 114688 + swz(row, j), Ql_g + row*64 + j*8);
        }
    }
    commitg(); waitg0();
    __syncthreads();   // mbarrier inits + Q visible to all

    // ---- prologue TMA: stages 0,1 <- KV tiles 0,1 ----
    if (t == 0) {
#pragma unroll
        for (int s = 0; s < 2; s++) {
            unsigned fb = mb + s * 8;
            unsigned dst = sbase + s * 32768;
            mbar_expect_tx(fb, 32768);
            int y = ybase + s * 64;
            tma2d(dst,         &mKh, 0, y, fb);
            tma2d(dst + 8192,  &mKl, 0, y, fb);
            tma2d(dst + 16384, &mVh, 0, y, fb);
            tma2d(dst + 24576, &mVl, 0, y, fb);
        }
    }

    // ---- Q fragments to registers ----
    unsigned qh[4][4], ql[4][4];
    int R0 = w * 16;
    {
        int mi = lane >> 3, rr = lane & 7;
#pragma unroll
        for (int kk = 0; kk < 4; kk++) {
            int rowq = R0 + (mi & 1) * 8 + rr;
            int jc = kk * 2 + (mi >> 1);
            unsigned a = sbase + 98304 + swz(rowq, jc);
            ldsm4(qh[kk], a);
            ldsm4(ql[kk], a + 16384);
        }
    }

    float O[8][4];
#pragma unroll
    for (int nt = 0; nt < 8; nt++)
#pragma unroll
        for (int j = 0; j < 4; j++) O[nt][j] = 0.0f;
    float m0 = -1e30f, m1 = -1e30f, l0 = 0.0f, l1 = 0.0f;

    for (int kt = 0; kt < 32; kt++) {
        int st = kt % 3;
        // ---- producer: refill stage (kt+2)%3 ----
        if (t == 0 && kt < 30) {
            int s2 = (kt + 2) % 3;
            if (kt >= 1) mbar_wait(mb + 24 + s2 * 8, (unsigned)(((kt - 1) / 3) & 1));
            unsigned fb = mb + s2 * 8;
            unsigned dst = sbase + (unsigned)s2 * 32768;
            mbar_expect_tx(fb, 32768);
            int y = ybase + (kt + 2) * 64;
            tma2d(dst,         &mKh, 0, y, fb);
            tma2d(dst + 8192,  &mKl, 0, y, fb);
            tma2d(dst + 16384, &mVh, 0, y, fb);
            tma2d(dst + 24576, &mVl, 0, y, fb);
        }
        // ---- consumer: wait stage ready ----
        mbar_wait(mb + st * 8, (unsigned)((kt / 3) & 1));
        unsigned sb = sbase + (unsigned)st * 32768;

        // ---- S = Q K^T (3-mma hi/lo) ----
        float S[8][4];
#pragma unroll
        for (int nt = 0; nt < 8; nt++)
#pragma unroll
            for (int j = 0; j < 4; j++) S[nt][j] = 0.0f;

        {
            int rr = lane & 7, q2 = lane >> 3;
            int rowbase = (q2 >> 1) * 8 + rr;
            int hf = q2 & 1;
#pragma unroll
            for (int ntp = 0; ntp < 4; ntp++) {
                int rowk = ntp * 16 + rowbase;
#pragma unroll
                for (int kk = 0; kk < 4; kk++) {
                    unsigned ka = sb + swz(rowk, kk * 2 + hf);
                    unsigned bh[4], bl[4];
                    ldsm4(bh, ka);
                    ldsm4(bl, ka + 8192);
                    int n0 = ntp * 2, n1 = ntp * 2 + 1;
                    mma16816(S[n0], qh[kk], bh[0], bh[1]);
                    mma16816(S[n1], qh[kk], bh[2], bh[3]);
                    mma16816(S[n0], qh[kk], bl[0], bl[1]);
                    mma16816(S[n1], qh[kk], bl[2], bl[3]);
                    mma16816(S[n0], ql[kk], bh[0], bh[1]);
                    mma16816(S[n1], ql[kk], bh[2], bh[3]);
                }
            }
        }

        // ---- online softmax ----
        float mx0 = -1e30f, mx1 = -1e30f;
#pragma unroll
        for (int nt = 0; nt < 8; nt++) {
            mx0 = fmaxf(mx0, fmaxf(S[nt][0], S[nt][1]));
            mx1 = fmaxf(mx1, fmaxf(S[nt][2], S[nt][3]));
        }
        mx0 = fmaxf(mx0, __shfl_xor_sync(0xffffffffu, mx0, 1));
        mx0 = fmaxf(mx0, __shfl_xor_sync(0xffffffffu, mx0, 2));
        mx1 = fmaxf(mx1, __shfl_xor_sync(0xffffffffu, mx1, 1));
        mx1 = fmaxf(mx1, __shfl_xor_sync(0xffffffffu, mx1, 2));
        float m0n = fmaxf(m0, mx0), m1n = fmaxf(m1, mx1);
        float al0 = fexp2((m0 - m0n) * C_EXP);
        float al1 = fexp2((m1 - m1n) * C_EXP);
        float mc0 = m0n * C_EXP, mc1 = m1n * C_EXP;
        l0 *= al0; l1 *= al1;
#pragma unroll
        for (int nt = 0; nt < 8; nt++) {
            float p0 = fexp2(fmaf(S[nt][0], C_EXP, -mc0));
            float p1 = fexp2(fmaf(S[nt][1], C_EXP, -mc0));
            float p2 = fexp2(fmaf(S[nt][2], C_EXP, -mc1));
            float p3 = fexp2(fmaf(S[nt][3], C_EXP, -mc1));
            l0 += p0 + p1; l1 += p2 + p3;
            S[nt][0] = p0; S[nt][1] = p1; S[nt][2] = p2; S[nt][3] = p3;
            O[nt][0] *= al0; O[nt][1] *= al0; O[nt][2] *= al1; O[nt][3] *= al1;
        }
        m0 = m0n; m1 = m1n;

        // ---- pack P into A-fragments (hi/lo) ----
        unsigned ph[4][4], pl[4][4];
#pragma unroll
        for (int tt = 0; tt < 4; tt++) {
            packsplit(S[2*tt][0],   S[2*tt][1],   ph[tt][0], pl[tt][0]);
            packsplit(S[2*tt][2],   S[2*tt][3],   ph[tt][1], pl[tt][1]);
            packsplit(S[2*tt+1][0], S[2*tt+1][1], ph[tt][2], pl[tt][2]);
            packsplit(S[2*tt+1][2], S[2*tt+1][3], ph[tt][3], pl[tt][3]);
        }

        // ---- O += P V ----
        {
            int vlr = lane & 15, vh2 = lane >> 4;
#pragma unroll
            for (int tt = 0; tt < 4; tt++) {
                int rowv = tt * 16 + vlr;
#pragma unroll
                for (int ndp = 0; ndp < 4; ndp++) {
                    unsigned va = sb + 16384 + swz(rowv, ndp * 2 + vh2);
                    unsigned vh[4], vl[4];
                    ldsm4t(vh, va);
                    ldsm4t(vl, va + 8192);
                    int n0 = ndp * 2, n1 = ndp * 2 + 1;
                    mma16816(O[n0], ph[tt], vh[0], vh[1]);
                    mma16816(O[n1], ph[tt], vh[2], vh[3]);
                    mma16816(O[n0], ph[tt], vl[0], vl[1]);
                    mma16816(O[n1], ph[tt], vl[2], vl[3]);
                    mma16816(O[n0], pl[tt], vh[0], vh[1]);
                    mma16816(O[n1], pl[tt], vh[2], vh[3]);
                }
            }
        }
        // ---- stage consumed (last MMAs issued => all smem reads done) ----
        if (lane == 0) mbar_arrive(mb + 24 + st * 8);
    }

    // ---- epilogue ----
    l0 += __shfl_xor_sync(0xffffffffu, l0, 1);
    l0 += __shfl_xor_sync(0xffffffffu, l0, 2);
    l1 += __shfl_xor_sync(0xffffffffu, l1, 1);
    l1 += __shfl_xor_sync(0xffffffffu, l1, 2);
    float inv0 = 1.0f / l0, inv1 = 1.0f / l1;

    int s_ = unit / (BB*NH);
    int bh_ = unit % (BB*NH);
    int bi = bh_ / NH, h = bh_ % NH;
    int tok0 = qblk * 128 + R0 + g;
    int tok1 = tok0 + 8;

#pragma unroll
    for (int nd = 0; nd < 8; nd++) {
        int d = nd * 8 + 2 * cc;
        unsigned hw, lw;
        size_t off0 = (size_t)s_ * MD + (size_t)(bi*SEQ + tok0) * DIMC + h*64 + d;
        packsplit(O[nd][0] * inv0, O[nd][1] * inv0, hw, lw);
        *(unsigned*)(g_ohi + off0) = hw;
        *(unsigned*)(g_olo + off0) = lw;
        size_t off1 = (size_t)s_ * MD + (size_t)(bi*SEQ + tok1) * DIMC + h*64 + d;
        packsplit(O[nd][2] * inv1, O[nd][3] * inv1, hw, lw);
        *(unsigned*)(g_ohi + off1) = hw;
        *(unsigned*)(g_olo + off1) = lw;
    }
}

// ---------------- host: tensor maps + launch ----------------------------------
typedef CUresult (*tme_t)(CUtensorMap*, CUtensorMapDataType, cuuint32_t, void*,
                          const cuuint64_t*, const cuuint64_t*, const cuuint32_t*,
                          const cuuint32_t*, CUtensorMapInterleave, CUtensorMapSwizzle,
                          CUtensorMapL2promotion, CUtensorMapFloatOOBfill);

static void make_kv_map(tme_t enc, CUtensorMap* m, void* addr) {
    cuuint64_t dims[2]    = {64ull, (cuuint64_t)UNITS * SEQ};
    cuuint64_t strides[1] = {128ull};
    cuuint32_t box[2]     = {64u, 64u};
    cuuint32_t es[2]      = {1u, 1u};
    enc(m, CU_TENSOR_MAP_DATA_TYPE_BFLOAT16, 2, addr, dims, strides, box, es,
        CU_TENSOR_MAP_INTERLEAVE_NONE, CU_TENSOR_MAP_SWIZZLE_128B,
        CU_TENSOR_MAP_L2_PROMOTION_L2_128B, CU_TENSOR_MAP_FLOAT_OOB_FILL_NONE);
}

extern "C" void kernel_launch(void* const* d_in, const int* in_sizes, int n_in,
                              void* d_out, int out_size) {
    const float* x1 = (const float*)d_in[0];
    const float* x2 = (const float*)d_in[1];
    const float* Wq = (const float*)d_in[2];
    const float* bq = (const float*)d_in[3];
    const float* Wk = (const float*)d_in[4];
    const float* bk = (const float*)d_in[5];
    const float* Wv = (const float*)d_in[6];
    const float* bv = (const float*)d_in[7];
    const float* Wo = (const float*)d_in[8];
    const float* bo = (const float*)d_in[9];
    const float* cs = (const float*)d_in[10];

    static CUtensorMap mKh, mKl, mVh, mVl;
    static bool made = false;
    if (!made) {
        void* fn = nullptr;
        cudaDriverEntryPointQueryResult qr;
        cudaGetDriverEntryPoint("cuTensorMapEncodeTiled", &fn, cudaEnableDefault, &qr);
        tme_t enc = (tme_t)fn;
        void* p;
        cudaGetSymbolAddress(&p, g_kh); make_kv_map(enc, &mKh, p);
        cudaGetSymbolAddress(&p, g_kl); make_kv_map(enc, &mKl, p);
        cudaGetSymbolAddress(&p, g_vh); make_kv_map(enc, &mVh, p);
        cudaGetSymbolAddress(&p, g_vl); make_kv_map(enc, &mVl, p);
        made = true;
    }

    cudaFuncSetAttribute(qkv_mma,   cudaFuncAttributeMaxDynamicSharedMemorySize, GEMM_SMEM);
    cudaFuncSetAttribute(oproj_mma, cudaFuncAttributeMaxDynamicSharedMemorySize, GEMM_SMEM);
    cudaFuncSetAttribute(attn_mma,  cudaFuncAttributeMaxDynamicSharedMemorySize, AT_SMEM);

    mixcvt_kernel<<<(MTOT * DIMC) / 256, 256>>>(x1, x2, cs);
    wcvt_kernel<<<dim3((DIMC * DIMC) / 256, 4), 256>>>(Wq, Wk, Wv, Wo);

    qkv_mma<<<dim3(6, 32, 6), 256, GEMM_SMEM>>>(bq, bk, bv);

    attn_mma<<<dim3(16, 48), 256, AT_SMEM>>>(mKh, mKl, mVh, mVl);

    oproj_mma<<<dim3(6, 32, 2), 256, GEMM_SMEM>>>(bo, (float*)d_out);
}